// round 7
// baseline (speedup 1.0000x reference)
#include <cuda_runtime.h>
#include <cuda_bf16.h>
#include <math.h>
#include <stddef.h>
#include <stdint.h>

// ---------------- problem constants ----------------
#define NUSR 50000
#define NITM 20000
#define NEDG 400000
#define FIN0 128
#define FHID 256
#define NHEAD 4

// ---------------- device scratch (no allocs allowed) ----------------
__device__ float g_hu [(size_t)NUSR * FHID];
__device__ float g_hi [(size_t)NITM * FHID];
__device__ float g_hsu[(size_t)NUSR * FHID];
__device__ float g_hsi[(size_t)NITM * FHID];
__device__ float g_nu [(size_t)NUSR * FHID];
__device__ float g_ni [(size_t)NITM * FHID];
__device__ float g_el_u[NUSR * 4];
__device__ float g_el_i[NITM * 4];
__device__ float g_er_u[NUSR * 4];
__device__ float g_er_i[NITM * 4];
__device__ int   g_rp_i[NITM + 1];
__device__ int   g_rp_u[NUSR + 1];
__device__ int   g_srcs_i[NEDG];
__device__ int   g_srcs_u[NEDG];
__device__ int   g_cur_i[NITM];
__device__ int   g_cur_u[NUSR];
__device__ float g_V1[FHID * NHEAD];
__device__ float g_V2[FHID * NHEAD];
__device__ float g_stats_i[2 * FHID];
__device__ float g_stats_u[2 * FHID];
__device__ int   g_part[64];
// pre-split weights: per side, layers packed [L0|L1|L2|L3] = 196608 elems
__device__ __nv_bfloat16 g_WHu[196608];
__device__ __nv_bfloat16 g_WLu[196608];
__device__ __nv_bfloat16 g_WHi[196608];
__device__ __nv_bfloat16 g_WLi[196608];
__device__ __nv_bfloat16 g_Auh[(size_t)NUSR * FHID];
__device__ __nv_bfloat16 g_Aul[(size_t)NUSR * FHID];
__device__ __nv_bfloat16 g_Aih[(size_t)NITM * FHID];
__device__ __nv_bfloat16 g_Ail[(size_t)NITM * FHID];

// ---------------- PTX helpers (baseline features only) ----------------
__device__ __forceinline__ uint32_t smem_u32(const void* p) {
    uint32_t a;
    asm("{ .reg .u64 t; cvta.to.shared.u64 t, %1; cvt.u32.u64 %0, t; }"
        : "=r"(a) : "l"(p));
    return a;
}
__device__ __forceinline__ void ldsm4(uint32_t* r, uint32_t addr) {
    asm volatile("ldmatrix.sync.aligned.m8n8.x4.shared.b16 {%0,%1,%2,%3}, [%4];"
        : "=r"(r[0]), "=r"(r[1]), "=r"(r[2]), "=r"(r[3]) : "r"(addr));
}
__device__ __forceinline__ void ldsm4t(uint32_t* r, uint32_t addr) {
    asm volatile("ldmatrix.sync.aligned.m8n8.x4.trans.shared.b16 {%0,%1,%2,%3}, [%4];"
        : "=r"(r[0]), "=r"(r[1]), "=r"(r[2]), "=r"(r[3]) : "r"(addr));
}
__device__ __forceinline__ void mma16816(float* c, const uint32_t* a,
                                         uint32_t b0, uint32_t b1) {
    asm volatile(
        "mma.sync.aligned.m16n8k16.row.col.f32.bf16.bf16.f32 "
        "{%0,%1,%2,%3}, {%4,%5,%6,%7}, {%8,%9}, {%0,%1,%2,%3};"
        : "+f"(c[0]), "+f"(c[1]), "+f"(c[2]), "+f"(c[3])
        : "r"(a[0]), "r"(a[1]), "r"(a[2]), "r"(a[3]), "r"(b0), "r"(b1));
}
#define CPA16(dst, src) \
    asm volatile("cp.async.cg.shared.global [%0], [%1], 16;" \
                 :: "r"(dst), "l"(src))
#define CP_COMMIT() asm volatile("cp.async.commit_group;")
#define CP_WAIT1()  asm volatile("cp.async.wait_group 1;" ::: "memory")
#define CP_WAIT0()  asm volatile("cp.async.wait_group 0;" ::: "memory")

// ---------------- tiny utility kernels ----------------
__global__ void k_noop() {}
__global__ void k_zeroi(int* p, int n) {
    int i = blockIdx.x * blockDim.x + threadIdx.x;
    if (i < n) p[i] = 0;
}
__global__ void k_copyi(const int* __restrict__ a, int* __restrict__ b, int n) {
    int i = blockIdx.x * blockDim.x + threadIdx.x;
    if (i < n) b[i] = a[i];
}

// ---------------- CSR construction ----------------
__global__ void k_count(const int* __restrict__ eu, const int* __restrict__ ei,
                        int* cu, int* ci) {
    int k = blockIdx.x * blockDim.x + threadIdx.x;
    if (k < NEDG) {
        atomicAdd(&ci[ei[k]], 1);
        atomicAdd(&cu[eu[k]], 1);
    }
}
__global__ void k_scan_blk(const int* __restrict__ cnt, int n,
                           int* __restrict__ rp, int* __restrict__ part) {
    __shared__ int ws[32];
    int tid = threadIdx.x;
    int i = blockIdx.x * 1024 + tid;
    int v = (i < n) ? cnt[i] : 0;
    int lane = tid & 31, w = tid >> 5;
    int x = v;
    #pragma unroll
    for (int o = 1; o < 32; o <<= 1) {
        int y = __shfl_up_sync(0xffffffffu, x, o);
        if (lane >= o) x += y;
    }
    if (lane == 31) ws[w] = x;
    __syncthreads();
    if (w == 0) {
        int t = ws[lane];
        #pragma unroll
        for (int o = 1; o < 32; o <<= 1) {
            int y = __shfl_up_sync(0xffffffffu, t, o);
            if (lane >= o) t += y;
        }
        ws[lane] = t;
    }
    __syncthreads();
    int incl = x + (w > 0 ? ws[w - 1] : 0);
    if (i < n) rp[i + 1] = incl;
    if (tid == 1023) part[blockIdx.x] = incl;
}
__global__ void k_scan_part(int* part, int nb) {
    __shared__ int w0sum;
    int tid = threadIdx.x;
    int v = (tid < nb) ? part[tid] : 0;
    int lane = tid & 31, w = tid >> 5;
    int x = v;
    #pragma unroll
    for (int o = 1; o < 32; o <<= 1) {
        int y = __shfl_up_sync(0xffffffffu, x, o);
        if (lane >= o) x += y;
    }
    if (w == 0 && lane == 31) w0sum = x;
    __syncthreads();
    int incl = x + (w ? w0sum : 0);
    if (tid < nb) part[tid] = incl - v;
}
__global__ void k_scan_add(int* __restrict__ rp, const int* __restrict__ part, int n) {
    int i = blockIdx.x * 1024 + threadIdx.x;
    if (i < n) rp[i + 1] += part[blockIdx.x];
    if (i == 0) rp[0] = 0;
}
__global__ void k_scatter(const int* __restrict__ eu, const int* __restrict__ ei,
                          int* cu, int* ci,
                          int* __restrict__ su, int* __restrict__ si) {
    int k = blockIdx.x * blockDim.x + threadIdx.x;
    if (k < NEDG) {
        int u = eu[k], it = ei[k];
        int p = atomicAdd(&ci[it], 1);
        si[p] = u;
        int q = atomicAdd(&cu[u], 1);
        su[q] = it;
    }
}

// ---------------- elementwise fp32 -> bf16 hi/lo split ----------------
__global__ void k_split(const float* __restrict__ X, __nv_bfloat16* __restrict__ xh,
                        __nv_bfloat16* __restrict__ xl, int total) {
    int id = blockIdx.x * blockDim.x + threadIdx.x;
    if (id >= total) return;
    float v = X[id];
    __nv_bfloat16 h = __float2bfloat16_rn(v);
    xh[id] = h;
    xl[id] = __float2bfloat16_rn(v - __bfloat162float(h));
}

// ---------------- tensor-core GEMM + fused el epilogue ----------------
template <int BN, int DH>
__global__ void __launch_bounds__((BN == 256) ? 512 : 256, 1)
k_mma_gemm(const __nv_bfloat16* __restrict__ Ah, const __nv_bfloat16* __restrict__ Al,
           const __nv_bfloat16* __restrict__ Bh, const __nv_bfloat16* __restrict__ Bl,
           const float* __restrict__ attA,
           float* __restrict__ C, float* __restrict__ el, int M, int K) {
    constexpr int NT = (BN == 256) ? 512 : 256;
    constexpr int SBSTR = BN * 2 + 16;
    constexpr int ASZ = 128 * 80;
    constexpr int BOFF = 2 * ASZ;
    constexpr int BSZ = 32 * SBSTR;
    constexpr int STAGE = BOFF + 2 * BSZ;
    constexpr int NBC = 32 * (BN / 8);

    extern __shared__ char smem[];
    uint32_t sb = smem_u32(smem);
    int tid = threadIdx.x;
    int wid = tid >> 5, lane = tid & 31;
    int wm = wid & 3, wn = wid >> 2;
    int bm = blockIdx.x * 128;

    float acc[2][8][4];
    #pragma unroll
    for (int i = 0; i < 2; i++)
        #pragma unroll
        for (int j = 0; j < 8; j++)
            #pragma unroll
            for (int q = 0; q < 4; q++) acc[i][j][q] = 0.f;

    int nch = K >> 5;

    auto load_stage = [&](int st, int kc) {
        uint32_t sbase = sb + st * STAGE;
        int k0 = kc << 5;
        #pragma unroll
        for (int c = tid; c < 512; c += NT) {
            int row = c >> 2, q = c & 3;
            int gr = bm + row;
            gr = gr < M ? gr : M - 1;
            size_t gi = (size_t)gr * K + k0 + q * 8;
            uint32_t d = sbase + row * 80 + q * 16;
            CPA16(d, Ah + gi);
            CPA16(d + ASZ, Al + gi);
        }
        #pragma unroll
        for (int c = tid; c < NBC; c += NT) {
            int k = c / (BN / 8), seg = c % (BN / 8);
            size_t gi = (size_t)(k0 + k) * BN + seg * 8;
            uint32_t d = sbase + BOFF + k * SBSTR + seg * 16;
            CPA16(d, Bh + gi);
            CPA16(d + BSZ, Bl + gi);
        }
        CP_COMMIT();
    };

    load_stage(0, 0);
    for (int kc = 0; kc < nch; kc++) {
        int cur = kc & 1;
        if (kc + 1 < nch) {
            load_stage(1 - cur, kc + 1);
            CP_WAIT1();
        } else {
            CP_WAIT0();
        }
        __syncthreads();
        uint32_t abase = sb + cur * STAGE;
        #pragma unroll
        for (int s = 0; s < 2; s++) {
            uint32_t Af[2][4], Alf[2][4];
            #pragma unroll
            for (int mt = 0; mt < 2; mt++) {
                uint32_t ad = abase +
                    (uint32_t)(wm * 32 + mt * 16 + (lane & 15)) * 80 +
                    s * 32 + (lane >> 4) * 16;
                ldsm4(Af[mt], ad);
                ldsm4(Alf[mt], ad + ASZ);
            }
            #pragma unroll
            for (int np = 0; np < 4; np++) {
                int g = lane >> 3, r = lane & 7;
                int kk = s * 16 + (g & 1) * 8 + r;
                int nn = wn * 64 + np * 16 + (g >> 1) * 8;
                uint32_t bd = abase + BOFF + (uint32_t)kk * SBSTR + nn * 2;
                uint32_t bh4[4], bl4[4];
                ldsm4t(bh4, bd);
                ldsm4t(bl4, bd + BSZ);
                #pragma unroll
                for (int mt = 0; mt < 2; mt++)
                    #pragma unroll
                    for (int sub = 0; sub < 2; sub++) {
                        float* a = acc[mt][np * 2 + sub];
                        mma16816(a, Af[mt], bh4[2 * sub], bh4[2 * sub + 1]);
                        mma16816(a, Af[mt], bl4[2 * sub], bl4[2 * sub + 1]);
                        mma16816(a, Alf[mt], bh4[2 * sub], bh4[2 * sub + 1]);
                    }
            }
        }
        __syncthreads();
    }

    constexpr int HPW = 64 / DH;
    int grp = lane >> 2, tq = lane & 3;
    #pragma unroll
    for (int mt = 0; mt < 2; mt++) {
        int r0 = bm + wm * 32 + mt * 16 + grp;
        int r1 = r0 + 8;
        #pragma unroll
        for (int nt = 0; nt < 8; nt++) {
            int col = wn * 64 + nt * 8 + tq * 2;
            if (r0 < M)
                *(float2*)(C + (size_t)r0 * BN + col) =
                    make_float2(acc[mt][nt][0], acc[mt][nt][1]);
            if (r1 < M)
                *(float2*)(C + (size_t)r1 * BN + col) =
                    make_float2(acc[mt][nt][2], acc[mt][nt][3]);
        }
        float s0[HPW], s1[HPW];
        #pragma unroll
        for (int p = 0; p < HPW; p++) { s0[p] = 0.f; s1[p] = 0.f; }
        #pragma unroll
        for (int nt = 0; nt < 8; nt++) {
            int part = (nt * 8) / DH;
            int col = wn * 64 + nt * 8 + tq * 2;
            float c0 = attA[col], c1 = attA[col + 1];
            s0[part] += c0 * acc[mt][nt][0] + c1 * acc[mt][nt][1];
            s1[part] += c0 * acc[mt][nt][2] + c1 * acc[mt][nt][3];
        }
        #pragma unroll
        for (int p = 0; p < HPW; p++) {
            s0[p] += __shfl_xor_sync(0xffffffffu, s0[p], 1);
            s0[p] += __shfl_xor_sync(0xffffffffu, s0[p], 2);
            s1[p] += __shfl_xor_sync(0xffffffffu, s1[p], 1);
            s1[p] += __shfl_xor_sync(0xffffffffu, s1[p], 2);
            if (tq == 0) {
                int h = wn * HPW + p;
                if (r0 < M) el[r0 * 4 + h] = s0[p];
                if (r1 < M) el[r1 * 4 + h] = s1[p];
            }
        }
    }
}

// ---------------- V[k,h] = sum_d W[k, h*dh+d] * A1[h,d] ----------------
__global__ void k_collapseV(const float* __restrict__ W, const float* __restrict__ A,
                            float* __restrict__ V, int fin, int F, int dh) {
    int t = blockIdx.x * blockDim.x + threadIdx.x;
    if (t >= fin * NHEAD) return;
    int k = t >> 2, h = t & 3;
    const float* A1 = A + NHEAD * dh;
    float s = 0.f;
    for (int d = 0; d < dh; d++)
        s += W[(size_t)k * F + h * dh + d] * A1[h * dh + d];
    V[t] = s;
}

// ---------------- er[n,:] = X[n,:] @ V ----------------
__global__ void k_er(const float* __restrict__ X, const float4* __restrict__ V4,
                     float* __restrict__ er, int n, int fin) {
    int w = (blockIdx.x * blockDim.x + threadIdx.x) >> 5;
    int lane = threadIdx.x & 31;
    if (w >= n) return;
    const float* x = X + (size_t)w * fin;
    float a0 = 0.f, a1 = 0.f, a2 = 0.f, a3 = 0.f;
    for (int k = lane; k < fin; k += 32) {
        float xv = x[k];
        float4 v = V4[k];
        a0 += xv * v.x; a1 += xv * v.y; a2 += xv * v.z; a3 += xv * v.w;
    }
    #pragma unroll
    for (int o = 16; o; o >>= 1) {
        a0 += __shfl_xor_sync(0xffffffffu, a0, o);
        a1 += __shfl_xor_sync(0xffffffffu, a1, o);
        a2 += __shfl_xor_sync(0xffffffffu, a2, o);
        a3 += __shfl_xor_sync(0xffffffffu, a3, o);
    }
    if (lane == 0) {
        er[w * 4 + 0] = a0; er[w * 4 + 1] = a1;
        er[w * 4 + 2] = a2; er[w * 4 + 3] = a3;
    }
}

__device__ __forceinline__ float lrelu(float x, float s) { return x > 0.f ? x : s * x; }

// ------- single-pass segment softmax + aggregation, F=256 (dh=64) -------
// softmax without max-shift (shift-invariant; |e| << 80 for this data).
// block 0 additionally zeroes the BN stats buffer for the following kernel.
__global__ void k_edge256(const int* __restrict__ rp, const int* __restrict__ srcs,
                          const float4* __restrict__ el4, const float4* __restrict__ er4,
                          const float* __restrict__ hs, float* __restrict__ out,
                          float* __restrict__ stats, int ndst) {
    if (stats != nullptr && blockIdx.x == 0) {
        stats[threadIdx.x] = 0.f;
        stats[256 + threadIdx.x] = 0.f;
    }
    int w = (blockIdx.x * blockDim.x + threadIdx.x) >> 5;
    int lane = threadIdx.x & 31;
    if (w >= ndst) return;
    int s0 = rp[w], s1 = rp[w + 1];
    float4* o = (float4*)(out + (size_t)w * 256);
    if (s0 == s1) {
        float4 z = make_float4(0.f, 0.f, 0.f, 0.f);
        o[lane] = z;
        o[lane + 32] = z;
        return;
    }
    float4 er = er4[w];
    bool loHalf = lane < 16;
    float erA = loHalf ? er.x : er.y, erB = loHalf ? er.z : er.w;

    float4 acc0 = make_float4(0.f, 0.f, 0.f, 0.f);
    float4 acc1 = make_float4(0.f, 0.f, 0.f, 0.f);
    float zA = 0.f, zB = 0.f;
    for (int j = s0; j < s1; j++) {
        int s = srcs[j];
        float4 e = el4[s];
        float eA = loHalf ? e.x : e.y, eB = loHalf ? e.z : e.w;
        float aA = expf(lrelu(eA + erA, 0.2f));
        float aB = expf(lrelu(eB + erB, 0.2f));
        const float4* row = (const float4*)(hs + (size_t)s * 256);
        float4 v0 = row[lane];
        float4 v1 = row[lane + 32];
        acc0.x += aA * v0.x; acc0.y += aA * v0.y; acc0.z += aA * v0.z; acc0.w += aA * v0.w;
        acc1.x += aB * v1.x; acc1.y += aB * v1.y; acc1.z += aB * v1.z; acc1.w += aB * v1.w;
        zA += aA; zB += aB;
    }
    float iA = 1.f / zA, iB = 1.f / zB;
    o[lane]      = make_float4(acc0.x * iA, acc0.y * iA, acc0.z * iA, acc0.w * iA);
    o[lane + 32] = make_float4(acc1.x * iB, acc1.y * iB, acc1.z * iB, acc1.w * iB);
}

// ------- single-pass segment softmax + aggregation, F=128 (dh=32) -------
__global__ void k_edge128(const int* __restrict__ rp, const int* __restrict__ srcs,
                          const float4* __restrict__ el4, const float4* __restrict__ er4,
                          const float* __restrict__ hs, float* __restrict__ out,
                          int ndst) {
    int w = (blockIdx.x * blockDim.x + threadIdx.x) >> 5;
    int lane = threadIdx.x & 31;
    if (w >= ndst) return;
    int s0 = rp[w], s1 = rp[w + 1];
    float4* o = (float4*)(out + (size_t)w * 128);
    if (s0 == s1) {
        o[lane] = make_float4(0.f, 0.f, 0.f, 0.f);
        return;
    }
    float4 er = er4[w];
    int hsel = lane >> 3;
    float erS = (hsel == 0) ? er.x : (hsel == 1) ? er.y : (hsel == 2) ? er.z : er.w;

    float4 acc = make_float4(0.f, 0.f, 0.f, 0.f);
    float z = 0.f;
    for (int j = s0; j < s1; j++) {
        int s = srcs[j];
        float4 e = el4[s];
        float eS = (hsel == 0) ? e.x : (hsel == 1) ? e.y : (hsel == 2) ? e.z : e.w;
        float a = expf(lrelu(eS + erS, 0.2f));
        const float4* row = (const float4*)(hs + (size_t)s * 128);
        float4 v = row[lane];
        acc.x += a * v.x; acc.y += a * v.y; acc.z += a * v.z; acc.w += a * v.w;
        z += a;
    }
    float iz = 1.f / z;
    o[lane] = make_float4(acc.x * iz, acc.y * iz, acc.z * iz, acc.w * iz);
}

// ---------------- BatchNorm ----------------
__global__ void k_bnstats(const float* __restrict__ x, float* __restrict__ stats, int n) {
    int c = threadIdx.x;
    float s = 0.f, q = 0.f;
    for (int r = blockIdx.x; r < n; r += gridDim.x) {
        float v = x[(size_t)r * 256 + c];
        s += v;
        q += v * v;
    }
    atomicAdd(&stats[c], s);
    atomicAdd(&stats[256 + c], q);
}

__global__ void k_bnapply(const float* __restrict__ x, float* __restrict__ y,
                          __nv_bfloat16* __restrict__ yh, __nv_bfloat16* __restrict__ yl,
                          const float* __restrict__ bn, const float* __restrict__ stats,
                          int L, int n, int use_tanh) {
    int c = threadIdx.x;
    float mu = stats[c] / (float)n;
    float var = stats[256 + c] / (float)n - mu * mu;
    float gamma = bn[(L * 2 + 0) * 256 + c];
    float beta  = bn[(L * 2 + 1) * 256 + c];
    float sc = gamma * rsqrtf(var + 1e-5f);
    float sh = beta - mu * sc;
    for (int r = blockIdx.x; r < n; r += gridDim.x) {
        size_t idx = (size_t)r * 256 + c;
        float v = sc * x[idx] + sh;
        v = use_tanh ? tanhf(v) : (v > 0.f ? v : 0.01f * v);
        y[idx] = v;
        __nv_bfloat16 h = __float2bfloat16_rn(v);
        yh[idx] = h;
        yl[idx] = __float2bfloat16_rn(v - __bfloat162float(h));
    }
}

// ---------------- static stream/event setup (pre-checkpoint) ----------------
namespace {
struct StreamInit {
    cudaStream_t s2 = 0;
    cudaEvent_t ev[32];
    bool ok = false;
    StreamInit() {
        if (cudaStreamCreateWithFlags(&s2, cudaStreamNonBlocking) != cudaSuccess) return;
        for (int i = 0; i < 32; i++)
            if (cudaEventCreateWithFlags(&ev[i], cudaEventDisableTiming) != cudaSuccess)
                return;
        k_noop<<<1, 32>>>();
        k_noop<<<1, 32, 0, s2>>>();
        for (int i = 0; i < 32; i++) cudaEventRecord(ev[i], (i & 1) ? s2 : 0);
        if (cudaDeviceSynchronize() != cudaSuccess) return;
        if (cudaGetLastError() != cudaSuccess) return;
        ok = true;
    }
};
StreamInit g_si;
}

// ---------------- host orchestration ----------------
static inline int wgrid(int nwarp) { return (nwarp * 32 + 255) / 256; }

struct Ptrs {
    float *hu, *hi, *hsu, *hsi, *nu, *ni;
    float *el_u, *el_i, *er_u, *er_i, *V1, *V2, *stats_i, *stats_u;
    __nv_bfloat16 *WHu, *WLu, *WHi, *WLi, *Auh, *Aul, *Aih, *Ail;
    int *rp_i, *rp_u, *srcs_i, *srcs_u, *cur_i, *cur_u, *part;
};

static void get_ptrs(Ptrs& p) {
    cudaGetSymbolAddress((void**)&p.hu, g_hu);
    cudaGetSymbolAddress((void**)&p.hi, g_hi);
    cudaGetSymbolAddress((void**)&p.hsu, g_hsu);
    cudaGetSymbolAddress((void**)&p.hsi, g_hsi);
    cudaGetSymbolAddress((void**)&p.nu, g_nu);
    cudaGetSymbolAddress((void**)&p.ni, g_ni);
    cudaGetSymbolAddress((void**)&p.el_u, g_el_u);
    cudaGetSymbolAddress((void**)&p.el_i, g_el_i);
    cudaGetSymbolAddress((void**)&p.er_u, g_er_u);
    cudaGetSymbolAddress((void**)&p.er_i, g_er_i);
    cudaGetSymbolAddress((void**)&p.V1, g_V1);
    cudaGetSymbolAddress((void**)&p.V2, g_V2);
    cudaGetSymbolAddress((void**)&p.stats_i, g_stats_i);
    cudaGetSymbolAddress((void**)&p.stats_u, g_stats_u);
    cudaGetSymbolAddress((void**)&p.WHu, g_WHu);
    cudaGetSymbolAddress((void**)&p.WLu, g_WLu);
    cudaGetSymbolAddress((void**)&p.WHi, g_WHi);
    cudaGetSymbolAddress((void**)&p.WLi, g_WLi);
    cudaGetSymbolAddress((void**)&p.Auh, g_Auh);
    cudaGetSymbolAddress((void**)&p.Aul, g_Aul);
    cudaGetSymbolAddress((void**)&p.Aih, g_Aih);
    cudaGetSymbolAddress((void**)&p.Ail, g_Ail);
    cudaGetSymbolAddress((void**)&p.rp_i, g_rp_i);
    cudaGetSymbolAddress((void**)&p.rp_u, g_rp_u);
    cudaGetSymbolAddress((void**)&p.srcs_i, g_srcs_i);
    cudaGetSymbolAddress((void**)&p.srcs_u, g_srcs_u);
    cudaGetSymbolAddress((void**)&p.cur_i, g_cur_i);
    cudaGetSymbolAddress((void**)&p.cur_u, g_cur_u);
    cudaGetSymbolAddress((void**)&p.part, g_part);
}

#define SMEM256 (2 * (2 * 128 * 80 + 2 * 32 * (256 * 2 + 16)))
#define SMEM128 (2 * (2 * 128 * 80 + 2 * 32 * (128 * 2 + 16)))

// packed weight offsets per layer (elements)
static const int WOFF[4] = {0, 32768, 98304, 163840};
static const int WSZ[4]  = {32768, 65536, 65536, 32768};

static void scan(const int* cnt, int n, int* rp, int* part, cudaStream_t st) {
    int nb = (n + 1023) / 1024;
    k_scan_blk<<<nb, 1024, 0, st>>>(cnt, n, rp, part);
    k_scan_part<<<1, 64, 0, st>>>(part, nb);
    k_scan_add<<<nb, 1024, 0, st>>>(rp, part, n);
}

extern "C" void kernel_launch(void* const* d_in, const int* in_sizes, int n_in,
                              void* d_out, int out_size) {
    Ptrs p;
    get_ptrs(p);
    cudaFuncSetAttribute(k_mma_gemm<256, 64>,
                         cudaFuncAttributeMaxDynamicSharedMemorySize, SMEM256);
    cudaFuncSetAttribute(k_mma_gemm<128, 32>,
                         cudaFuncAttributeMaxDynamicSharedMemorySize, SMEM128);

    const float* x_user = (const float*)d_in[0];
    const float* x_item = (const float*)d_in[1];
    const int*   eu     = (const int*)d_in[2];
    const int*   ei     = (const int*)d_in[3];

    bool dictOrder = (in_sizes[5] < 10000);
    const float *Wui[4], *Aui[4], *Wiu[4], *Aiu[4];
    for (int L = 0; L < 4; L++) {
        if (dictOrder) {
            Wui[L] = (const float*)d_in[4 + L * 4 + 0];
            Aui[L] = (const float*)d_in[4 + L * 4 + 1];
            Wiu[L] = (const float*)d_in[4 + L * 4 + 2];
            Aiu[L] = (const float*)d_in[4 + L * 4 + 3];
        } else {
            Wui[L] = (const float*)d_in[4 + L * 4 + 0];
            Wiu[L] = (const float*)d_in[4 + L * 4 + 1];
            Aui[L] = (const float*)d_in[4 + L * 4 + 2];
            Aiu[L] = (const float*)d_in[4 + L * 4 + 3];
        }
    }
    const float* bn_u = (const float*)d_in[20];
    const float* bn_i = (const float*)d_in[21];
    float* out = (float*)d_out;

    cudaStream_t SA = 0;
    cudaStream_t SB = g_si.ok ? g_si.s2 : (cudaStream_t)0;
    bool fork = g_si.ok;
    int ec = 0;
    auto REC = [&](cudaStream_t st) -> int {
        if (!fork) return -1;
        int i = ec++;
        cudaEventRecord(g_si.ev[i], st);
        return i;
    };
    auto WAITE = [&](cudaStream_t st, int i) {
        if (fork && i >= 0) cudaStreamWaitEvent(st, g_si.ev[i], 0);
    };

    // ---- capture-legal fork ----
    int evFork = REC(SA);
    WAITE(SB, evFork);

    // ---- pre-split all weights (SA: ui, SB: iu) ----
    for (int L = 0; L < 4; L++) {
        k_split<<<(WSZ[L] + 255) / 256, 256, 0, SA>>>(Wui[L], p.WHu + WOFF[L],
                                                      p.WLu + WOFF[L], WSZ[L]);
        k_split<<<(WSZ[L] + 255) / 256, 256, 0, SB>>>(Wiu[L], p.WHi + WOFF[L],
                                                      p.WLi + WOFF[L], WSZ[L]);
    }

    // ---- layer-0 input splits ----
    k_split<<<(NUSR * FIN0 + 255) / 256, 256, 0, SA>>>(x_user, p.Auh, p.Aul, NUSR * FIN0);
    k_split<<<(NITM * FIN0 + 255) / 256, 256, 0, SB>>>(x_item, p.Aih, p.Ail, NITM * FIN0);

    // ---- CSR build on SB ----
    k_zeroi<<<(NUSR + 255) / 256, 256, 0, SB>>>(p.cur_u, NUSR);
    k_zeroi<<<(NITM + 255) / 256, 256, 0, SB>>>(p.cur_i, NITM);
    k_count<<<(NEDG + 255) / 256, 256, 0, SB>>>(eu, ei, p.cur_u, p.cur_i);
    scan(p.cur_i, NITM, p.rp_i, p.part, SB);
    scan(p.cur_u, NUSR, p.rp_u, p.part, SB);
    k_copyi<<<(NITM + 255) / 256, 256, 0, SB>>>(p.rp_i, p.cur_i, NITM);
    k_copyi<<<(NUSR + 255) / 256, 256, 0, SB>>>(p.rp_u, p.cur_u, NUSR);
    k_scatter<<<(NEDG + 255) / 256, 256, 0, SB>>>(eu, ei, p.cur_u, p.cur_i,
                                                  p.srcs_u, p.srcs_i);
    int evCSR = REC(SB);

    const float* cu = x_user;
    const float* ci = x_item;
    int fin = FIN0;
    for (int L = 0; L < 4; L++) {
        int F = (L == 3) ? 128 : 256;
        int dh = (L == 3) ? 32 : 64;
        float* outi = (L == 3) ? (out + (size_t)NUSR * 128) : p.ni;
        float* outu = (L == 3) ? out : p.nu;
        int gbU = (NUSR + 127) / 128, gbI = (NITM + 127) / 128;

        // ---- SA: user GEMM (+el_u) ----
        if (F == 256)
            k_mma_gemm<256, 64><<<gbU, 512, SMEM256, SA>>>(p.Auh, p.Aul,
                p.WHu + WOFF[L], p.WLu + WOFF[L], Aui[L], p.hsu, p.el_u, NUSR, fin);
        else
            k_mma_gemm<128, 32><<<gbU, 256, SMEM128, SA>>>(p.Auh, p.Aul,
                p.WHu + WOFF[L], p.WLu + WOFF[L], Aui[L], p.hsu, p.el_u, NUSR, fin);
        int evAg = REC(SA);

        // ---- SB: item GEMM (+el_i), then all er feeders ----
        if (F == 256)
            k_mma_gemm<256, 64><<<gbI, 512, SMEM256, SB>>>(p.Aih, p.Ail,
                p.WHi + WOFF[L], p.WLi + WOFF[L], Aiu[L], p.hsi, p.el_i, NITM, fin);
        else
            k_mma_gemm<128, 32><<<gbI, 256, SMEM128, SB>>>(p.Aih, p.Ail,
                p.WHi + WOFF[L], p.WLi + WOFF[L], Aiu[L], p.hsi, p.el_i, NITM, fin);
        int evBg = REC(SB);
        k_collapseV<<<(fin * 4 + 255) / 256, 256, 0, SB>>>(Wiu[L], Aiu[L], p.V2,
                                                           fin, F, dh);
        k_er<<<wgrid(NUSR), 256, 0, SB>>>(cu, (const float4*)p.V2, p.er_u, NUSR, fin);
        k_collapseV<<<(fin * 4 + 255) / 256, 256, 0, SB>>>(Wui[L], Aui[L], p.V1,
                                                           fin, F, dh);
        k_er<<<wgrid(NITM), 256, 0, SB>>>(ci, (const float4*)p.V1, p.er_i, NITM, fin);
        int evERi = REC(SB);

        // ---- edges: item-dst on SA, user-dst on SB ----
        if (L == 0) WAITE(SA, evCSR);
        WAITE(SA, evERi);
        if (F == 256) {
            k_edge256<<<wgrid(NITM), 256, 0, SA>>>(p.rp_i, p.srcs_i,
                (const float4*)p.el_u, (const float4*)p.er_i, p.hsu, outi,
                (L < 3) ? p.stats_i : nullptr, NITM);
            k_edge256<<<wgrid(NUSR), 256, 0, SB>>>(p.rp_u, p.srcs_u,
                (const float4*)p.el_i, (const float4*)p.er_u, p.hsi, outu,
                (L < 3) ? p.stats_u : nullptr, NUSR);
        } else {
            k_edge128<<<wgrid(NITM), 256, 0, SA>>>(p.rp_i, p.srcs_i,
                (const float4*)p.el_u, (const float4*)p.er_i, p.hsu, outi, NITM);
            k_edge128<<<wgrid(NUSR), 256, 0, SB>>>(p.rp_u, p.srcs_u,
                (const float4*)p.el_i, (const float4*)p.er_u, p.hsi, outu, NUSR);
        }

        if (L < 3) {
            // BN item on SA (stats_i zeroed by edge256 block 0)
            k_bnstats<<<256, 256, 0, SA>>>(p.ni, p.stats_i, NITM);
            WAITE(SA, evBg);   // bnapply writes Aih/Ail read by SB's gemm
            k_bnapply<<<256, 256, 0, SA>>>(p.ni, p.hi, p.Aih, p.Ail, bn_i,
                                           p.stats_i, L, NITM, (L == 2) ? 1 : 0);
            // BN user on SB
            k_bnstats<<<256, 256, 0, SB>>>(p.nu, p.stats_u, NUSR);
            WAITE(SB, evAg);   // bnapply writes Auh/Aul read by SA's gemm
            k_bnapply<<<256, 256, 0, SB>>>(p.nu, p.hu, p.Auh, p.Aul, bn_u,
                                           p.stats_u, L, NUSR, (L == 2) ? 1 : 0);
            // layer-boundary cross joins
            int evAe = REC(SA);
            int evBe = REC(SB);
            WAITE(SA, evBe);   // next SA gemm reads Auh/Aul (made on SB)
            WAITE(SB, evAe);   // next SB gemm + er_i read Aih/Ail, hi (made on SA)
            cu = p.hu;
            ci = p.hi;
            fin = FHID;
        } else {
            // final join back into the capturing stream
            int evBf = REC(SB);
            WAITE(SA, evBf);
        }
    }
    (void)n_in; (void)out_size;
}

// round 8
// speedup vs baseline: 1.0481x; 1.0481x over previous
#include <cuda_runtime.h>
#include <cuda_bf16.h>
#include <math.h>
#include <stddef.h>
#include <stdint.h>

// ---------------- problem constants ----------------
#define NUSR 50000
#define NITM 20000
#define NEDG 400000
#define FIN0 128
#define FHID 256
#define NHEAD 4

// ---------------- device scratch (no allocs allowed) ----------------
__device__ float g_hu [(size_t)NUSR * FHID];
__device__ float g_hi [(size_t)NITM * FHID];
__device__ float g_hsu[(size_t)NUSR * FHID];
__device__ float g_hsi[(size_t)NITM * FHID];
__device__ float g_nu [(size_t)NUSR * FHID];
__device__ float g_ni [(size_t)NITM * FHID];
__device__ float g_el_u[NUSR * 4];
__device__ float g_el_i[NITM * 4];
__device__ float g_er_u[NUSR * 4];
__device__ float g_er_i[NITM * 4];
__device__ int   g_rp_i[NITM + 1];
__device__ int   g_rp_u[NUSR + 1];
__device__ int   g_srcs_i[NEDG];
__device__ int   g_srcs_u[NEDG];
__device__ int   g_cur_i[NITM];
__device__ int   g_cur_u[NUSR];
__device__ float g_Vui[4 * FHID * NHEAD];   // per-layer collapsed V, user->item
__device__ float g_Viu[4 * FHID * NHEAD];   // per-layer collapsed V, item->user
__device__ float g_stats_i[2 * FHID];
__device__ float g_stats_u[2 * FHID];
__device__ int   g_part[64];
__device__ __nv_bfloat16 g_WHu[196608];
__device__ __nv_bfloat16 g_WLu[196608];
__device__ __nv_bfloat16 g_WHi[196608];
__device__ __nv_bfloat16 g_WLi[196608];
__device__ __nv_bfloat16 g_Auh[(size_t)NUSR * FHID];
__device__ __nv_bfloat16 g_Aul[(size_t)NUSR * FHID];
__device__ __nv_bfloat16 g_Aih[(size_t)NITM * FHID];
__device__ __nv_bfloat16 g_Ail[(size_t)NITM * FHID];

// ---------------- PTX helpers (baseline features only) ----------------
__device__ __forceinline__ uint32_t smem_u32(const void* p) {
    uint32_t a;
    asm("{ .reg .u64 t; cvta.to.shared.u64 t, %1; cvt.u32.u64 %0, t; }"
        : "=r"(a) : "l"(p));
    return a;
}
__device__ __forceinline__ void ldsm4(uint32_t* r, uint32_t addr) {
    asm volatile("ldmatrix.sync.aligned.m8n8.x4.shared.b16 {%0,%1,%2,%3}, [%4];"
        : "=r"(r[0]), "=r"(r[1]), "=r"(r[2]), "=r"(r[3]) : "r"(addr));
}
__device__ __forceinline__ void ldsm4t(uint32_t* r, uint32_t addr) {
    asm volatile("ldmatrix.sync.aligned.m8n8.x4.trans.shared.b16 {%0,%1,%2,%3}, [%4];"
        : "=r"(r[0]), "=r"(r[1]), "=r"(r[2]), "=r"(r[3]) : "r"(addr));
}
__device__ __forceinline__ void mma16816(float* c, const uint32_t* a,
                                         uint32_t b0, uint32_t b1) {
    asm volatile(
        "mma.sync.aligned.m16n8k16.row.col.f32.bf16.bf16.f32 "
        "{%0,%1,%2,%3}, {%4,%5,%6,%7}, {%8,%9}, {%0,%1,%2,%3};"
        : "+f"(c[0]), "+f"(c[1]), "+f"(c[2]), "+f"(c[3])
        : "r"(a[0]), "r"(a[1]), "r"(a[2]), "r"(a[3]), "r"(b0), "r"(b1));
}
#define CPA16(dst, src) \
    asm volatile("cp.async.cg.shared.global [%0], [%1], 16;" \
                 :: "r"(dst), "l"(src))
#define CP_COMMIT() asm volatile("cp.async.commit_group;")
#define CP_WAIT1()  asm volatile("cp.async.wait_group 1;" ::: "memory")
#define CP_WAIT0()  asm volatile("cp.async.wait_group 0;" ::: "memory")

// ---------------- tiny utility kernels ----------------
__global__ void k_noop() {}
__global__ void k_zeroi(int* p, int n) {
    int i = blockIdx.x * blockDim.x + threadIdx.x;
    if (i < n) p[i] = 0;
}
__global__ void k_copyi(const int* __restrict__ a, int* __restrict__ b, int n) {
    int i = blockIdx.x * blockDim.x + threadIdx.x;
    if (i < n) b[i] = a[i];
}

// ---------------- CSR construction ----------------
__global__ void k_count(const int* __restrict__ eu, const int* __restrict__ ei,
                        int* cu, int* ci) {
    int k = blockIdx.x * blockDim.x + threadIdx.x;
    if (k < NEDG) {
        atomicAdd(&ci[ei[k]], 1);
        atomicAdd(&cu[eu[k]], 1);
    }
}
__global__ void k_scan_blk(const int* __restrict__ cnt, int n,
                           int* __restrict__ rp, int* __restrict__ part) {
    __shared__ int ws[32];
    int tid = threadIdx.x;
    int i = blockIdx.x * 1024 + tid;
    int v = (i < n) ? cnt[i] : 0;
    int lane = tid & 31, w = tid >> 5;
    int x = v;
    #pragma unroll
    for (int o = 1; o < 32; o <<= 1) {
        int y = __shfl_up_sync(0xffffffffu, x, o);
        if (lane >= o) x += y;
    }
    if (lane == 31) ws[w] = x;
    __syncthreads();
    if (w == 0) {
        int t = ws[lane];
        #pragma unroll
        for (int o = 1; o < 32; o <<= 1) {
            int y = __shfl_up_sync(0xffffffffu, t, o);
            if (lane >= o) t += y;
        }
        ws[lane] = t;
    }
    __syncthreads();
    int incl = x + (w > 0 ? ws[w - 1] : 0);
    if (i < n) rp[i + 1] = incl;
    if (tid == 1023) part[blockIdx.x] = incl;
}
__global__ void k_scan_part(int* part, int nb) {
    __shared__ int w0sum;
    int tid = threadIdx.x;
    int v = (tid < nb) ? part[tid] : 0;
    int lane = tid & 31, w = tid >> 5;
    int x = v;
    #pragma unroll
    for (int o = 1; o < 32; o <<= 1) {
        int y = __shfl_up_sync(0xffffffffu, x, o);
        if (lane >= o) x += y;
    }
    if (w == 0 && lane == 31) w0sum = x;
    __syncthreads();
    int incl = x + (w ? w0sum : 0);
    if (tid < nb) part[tid] = incl - v;
}
__global__ void k_scan_add(int* __restrict__ rp, const int* __restrict__ part, int n) {
    int i = blockIdx.x * 1024 + threadIdx.x;
    if (i < n) rp[i + 1] += part[blockIdx.x];
    if (i == 0) rp[0] = 0;
}
__global__ void k_scatter(const int* __restrict__ eu, const int* __restrict__ ei,
                          int* cu, int* ci,
                          int* __restrict__ su, int* __restrict__ si) {
    int k = blockIdx.x * blockDim.x + threadIdx.x;
    if (k < NEDG) {
        int u = eu[k], it = ei[k];
        int p = atomicAdd(&ci[it], 1);
        si[p] = u;
        int q = atomicAdd(&cu[u], 1);
        su[q] = it;
    }
}

// ---------------- elementwise fp32 -> bf16 hi/lo split ----------------
__global__ void k_split(const float* __restrict__ X, __nv_bfloat16* __restrict__ xh,
                        __nv_bfloat16* __restrict__ xl, int total) {
    int id = blockIdx.x * blockDim.x + threadIdx.x;
    if (id >= total) return;
    float v = X[id];
    __nv_bfloat16 h = __float2bfloat16_rn(v);
    xh[id] = h;
    xl[id] = __float2bfloat16_rn(v - __bfloat162float(h));
}

// ---------------- tensor-core GEMM + fused el epilogue ----------------
template <int BN, int DH>
__global__ void __launch_bounds__((BN == 256) ? 512 : 256, 1)
k_mma_gemm(const __nv_bfloat16* __restrict__ Ah, const __nv_bfloat16* __restrict__ Al,
           const __nv_bfloat16* __restrict__ Bh, const __nv_bfloat16* __restrict__ Bl,
           const float* __restrict__ attA,
           float* __restrict__ C, float* __restrict__ el, int M, int K) {
    constexpr int NT = (BN == 256) ? 512 : 256;
    constexpr int SBSTR = BN * 2 + 16;
    constexpr int ASZ = 128 * 80;
    constexpr int BOFF = 2 * ASZ;
    constexpr int BSZ = 32 * SBSTR;
    constexpr int STAGE = BOFF + 2 * BSZ;
    constexpr int NBC = 32 * (BN / 8);

    extern __shared__ char smem[];
    uint32_t sb = smem_u32(smem);
    int tid = threadIdx.x;
    int wid = tid >> 5, lane = tid & 31;
    int wm = wid & 3, wn = wid >> 2;
    int bm = blockIdx.x * 128;

    float acc[2][8][4];
    #pragma unroll
    for (int i = 0; i < 2; i++)
        #pragma unroll
        for (int j = 0; j < 8; j++)
            #pragma unroll
            for (int q = 0; q < 4; q++) acc[i][j][q] = 0.f;

    int nch = K >> 5;

    auto load_stage = [&](int st, int kc) {
        uint32_t sbase = sb + st * STAGE;
        int k0 = kc << 5;
        #pragma unroll
        for (int c = tid; c < 512; c += NT) {
            int row = c >> 2, q = c & 3;
            int gr = bm + row;
            gr = gr < M ? gr : M - 1;
            size_t gi = (size_t)gr * K + k0 + q * 8;
            uint32_t d = sbase + row * 80 + q * 16;
            CPA16(d, Ah + gi);
            CPA16(d + ASZ, Al + gi);
        }
        #pragma unroll
        for (int c = tid; c < NBC; c += NT) {
            int k = c / (BN / 8), seg = c % (BN / 8);
            size_t gi = (size_t)(k0 + k) * BN + seg * 8;
            uint32_t d = sbase + BOFF + k * SBSTR + seg * 16;
            CPA16(d, Bh + gi);
            CPA16(d + BSZ, Bl + gi);
        }
        CP_COMMIT();
    };

    load_stage(0, 0);
    for (int kc = 0; kc < nch; kc++) {
        int cur = kc & 1;
        if (kc + 1 < nch) {
            load_stage(1 - cur, kc + 1);
            CP_WAIT1();
        } else {
            CP_WAIT0();
        }
        __syncthreads();
        uint32_t abase = sb + cur * STAGE;
        #pragma unroll
        for (int s = 0; s < 2; s++) {
            uint32_t Af[2][4], Alf[2][4];
            #pragma unroll
            for (int mt = 0; mt < 2; mt++) {
                uint32_t ad = abase +
                    (uint32_t)(wm * 32 + mt * 16 + (lane & 15)) * 80 +
                    s * 32 + (lane >> 4) * 16;
                ldsm4(Af[mt], ad);
                ldsm4(Alf[mt], ad + ASZ);
            }
            #pragma unroll
            for (int np = 0; np < 4; np++) {
                int g = lane >> 3, r = lane & 7;
                int kk = s * 16 + (g & 1) * 8 + r;
                int nn = wn * 64 + np * 16 + (g >> 1) * 8;
                uint32_t bd = abase + BOFF + (uint32_t)kk * SBSTR + nn * 2;
                uint32_t bh4[4], bl4[4];
                ldsm4t(bh4, bd);
                ldsm4t(bl4, bd + BSZ);
                #pragma unroll
                for (int mt = 0; mt < 2; mt++)
                    #pragma unroll
                    for (int sub = 0; sub < 2; sub++) {
                        float* a = acc[mt][np * 2 + sub];
                        mma16816(a, Af[mt], bh4[2 * sub], bh4[2 * sub + 1]);
                        mma16816(a, Af[mt], bl4[2 * sub], bl4[2 * sub + 1]);
                        mma16816(a, Alf[mt], bh4[2 * sub], bh4[2 * sub + 1]);
                    }
            }
        }
        __syncthreads();
    }

    constexpr int HPW = 64 / DH;
    int grp = lane >> 2, tq = lane & 3;
    #pragma unroll
    for (int mt = 0; mt < 2; mt++) {
        int r0 = bm + wm * 32 + mt * 16 + grp;
        int r1 = r0 + 8;
        #pragma unroll
        for (int nt = 0; nt < 8; nt++) {
            int col = wn * 64 + nt * 8 + tq * 2;
            if (r0 < M)
                *(float2*)(C + (size_t)r0 * BN + col) =
                    make_float2(acc[mt][nt][0], acc[mt][nt][1]);
            if (r1 < M)
                *(float2*)(C + (size_t)r1 * BN + col) =
                    make_float2(acc[mt][nt][2], acc[mt][nt][3]);
        }
        float s0[HPW], s1[HPW];
        #pragma unroll
        for (int p = 0; p < HPW; p++) { s0[p] = 0.f; s1[p] = 0.f; }
        #pragma unroll
        for (int nt = 0; nt < 8; nt++) {
            int part = (nt * 8) / DH;
            int col = wn * 64 + nt * 8 + tq * 2;
            float c0 = attA[col], c1 = attA[col + 1];
            s0[part] += c0 * acc[mt][nt][0] + c1 * acc[mt][nt][1];
            s1[part] += c0 * acc[mt][nt][2] + c1 * acc[mt][nt][3];
        }
        #pragma unroll
        for (int p = 0; p < HPW; p++) {
            s0[p] += __shfl_xor_sync(0xffffffffu, s0[p], 1);
            s0[p] += __shfl_xor_sync(0xffffffffu, s0[p], 2);
            s1[p] += __shfl_xor_sync(0xffffffffu, s1[p], 1);
            s1[p] += __shfl_xor_sync(0xffffffffu, s1[p], 2);
            if (tq == 0) {
                int h = wn * HPW + p;
                if (r0 < M) el[r0 * 4 + h] = s0[p];
                if (r1 < M) el[r1 * 4 + h] = s1[p];
            }
        }
    }
}

// ---------------- V[k,h] = sum_d W[k, h*dh+d] * A1[h,d] ----------------
__global__ void k_collapseV(const float* __restrict__ W, const float* __restrict__ A,
                            float* __restrict__ V, int fin, int F, int dh) {
    int t = blockIdx.x * blockDim.x + threadIdx.x;
    if (t >= fin * NHEAD) return;
    int k = t >> 2, h = t & 3;
    const float* A1 = A + NHEAD * dh;
    float s = 0.f;
    for (int d = 0; d < dh; d++)
        s += W[(size_t)k * F + h * dh + d] * A1[h * dh + d];
    V[t] = s;
}

// ---------------- er[n,:] = X[n,:] @ V ----------------
__global__ void k_er(const float* __restrict__ X, const float4* __restrict__ V4,
                     float* __restrict__ er, int n, int fin) {
    int w = (blockIdx.x * blockDim.x + threadIdx.x) >> 5;
    int lane = threadIdx.x & 31;
    if (w >= n) return;
    const float* x = X + (size_t)w * fin;
    float a0 = 0.f, a1 = 0.f, a2 = 0.f, a3 = 0.f;
    for (int k = lane; k < fin; k += 32) {
        float xv = x[k];
        float4 v = V4[k];
        a0 += xv * v.x; a1 += xv * v.y; a2 += xv * v.z; a3 += xv * v.w;
    }
    #pragma unroll
    for (int o = 16; o; o >>= 1) {
        a0 += __shfl_xor_sync(0xffffffffu, a0, o);
        a1 += __shfl_xor_sync(0xffffffffu, a1, o);
        a2 += __shfl_xor_sync(0xffffffffu, a2, o);
        a3 += __shfl_xor_sync(0xffffffffu, a3, o);
    }
    if (lane == 0) {
        er[w * 4 + 0] = a0; er[w * 4 + 1] = a1;
        er[w * 4 + 2] = a2; er[w * 4 + 3] = a3;
    }
}

__device__ __forceinline__ float lrelu(float x, float s) { return x > 0.f ? x : s * x; }

// ------- single-pass segment softmax + aggregation, F=256 (dh=64) -------
__global__ void k_edge256(const int* __restrict__ rp, const int* __restrict__ srcs,
                          const float4* __restrict__ el4, const float4* __restrict__ er4,
                          const float* __restrict__ hs, float* __restrict__ out,
                          float* __restrict__ stats, int ndst) {
    if (stats != nullptr && blockIdx.x == 0) {
        stats[threadIdx.x] = 0.f;
        stats[256 + threadIdx.x] = 0.f;
    }
    int w = (blockIdx.x * blockDim.x + threadIdx.x) >> 5;
    int lane = threadIdx.x & 31;
    if (w >= ndst) return;
    int s0 = rp[w], s1 = rp[w + 1];
    float4* o = (float4*)(out + (size_t)w * 256);
    if (s0 == s1) {
        float4 z = make_float4(0.f, 0.f, 0.f, 0.f);
        o[lane] = z;
        o[lane + 32] = z;
        return;
    }
    float4 er = er4[w];
    bool loHalf = lane < 16;
    float erA = loHalf ? er.x : er.y, erB = loHalf ? er.z : er.w;

    float4 acc0 = make_float4(0.f, 0.f, 0.f, 0.f);
    float4 acc1 = make_float4(0.f, 0.f, 0.f, 0.f);
    float zA = 0.f, zB = 0.f;
    for (int j = s0; j < s1; j++) {
        int s = srcs[j];
        float4 e = el4[s];
        float eA = loHalf ? e.x : e.y, eB = loHalf ? e.z : e.w;
        float aA = expf(lrelu(eA + erA, 0.2f));
        float aB = expf(lrelu(eB + erB, 0.2f));
        const float4* row = (const float4*)(hs + (size_t)s * 256);
        float4 v0 = row[lane];
        float4 v1 = row[lane + 32];
        acc0.x += aA * v0.x; acc0.y += aA * v0.y; acc0.z += aA * v0.z; acc0.w += aA * v0.w;
        acc1.x += aB * v1.x; acc1.y += aB * v1.y; acc1.z += aB * v1.z; acc1.w += aB * v1.w;
        zA += aA; zB += aB;
    }
    float iA = 1.f / zA, iB = 1.f / zB;
    o[lane]      = make_float4(acc0.x * iA, acc0.y * iA, acc0.z * iA, acc0.w * iA);
    o[lane + 32] = make_float4(acc1.x * iB, acc1.y * iB, acc1.z * iB, acc1.w * iB);
}

// ------- single-pass segment softmax + aggregation, F=128 (dh=32) -------
__global__ void k_edge128(const int* __restrict__ rp, const int* __restrict__ srcs,
                          const float4* __restrict__ el4, const float4* __restrict__ er4,
                          const float* __restrict__ hs, float* __restrict__ out,
                          int ndst) {
    int w = (blockIdx.x * blockDim.x + threadIdx.x) >> 5;
    int lane = threadIdx.x & 31;
    if (w >= ndst) return;
    int s0 = rp[w], s1 = rp[w + 1];
    float4* o = (float4*)(out + (size_t)w * 128);
    if (s0 == s1) {
        o[lane] = make_float4(0.f, 0.f, 0.f, 0.f);
        return;
    }
    float4 er = er4[w];
    int hsel = lane >> 3;
    float erS = (hsel == 0) ? er.x : (hsel == 1) ? er.y : (hsel == 2) ? er.z : er.w;

    float4 acc = make_float4(0.f, 0.f, 0.f, 0.f);
    float z = 0.f;
    for (int j = s0; j < s1; j++) {
        int s = srcs[j];
        float4 e = el4[s];
        float eS = (hsel == 0) ? e.x : (hsel == 1) ? e.y : (hsel == 2) ? e.z : e.w;
        float a = expf(lrelu(eS + erS, 0.2f));
        const float4* row = (const float4*)(hs + (size_t)s * 128);
        float4 v = row[lane];
        acc.x += a * v.x; acc.y += a * v.y; acc.z += a * v.z; acc.w += a * v.w;
        z += a;
    }
    float iz = 1.f / z;
    o[lane] = make_float4(acc.x * iz, acc.y * iz, acc.z * iz, acc.w * iz);
}

// ---------------- BatchNorm ----------------
__global__ void k_bnstats(const float* __restrict__ x, float* __restrict__ stats, int n) {
    int c = threadIdx.x;
    float s = 0.f, q = 0.f;
    for (int r = blockIdx.x; r < n; r += gridDim.x) {
        float v = x[(size_t)r * 256 + c];
        s += v;
        q += v * v;
    }
    atomicAdd(&stats[c], s);
    atomicAdd(&stats[256 + c], q);
}

__global__ void k_bnapply(const float* __restrict__ x, float* __restrict__ y,
                          __nv_bfloat16* __restrict__ yh, __nv_bfloat16* __restrict__ yl,
                          const float* __restrict__ bn, const float* __restrict__ stats,
                          int L, int n, int use_tanh) {
    int c = threadIdx.x;
    float mu = stats[c] / (float)n;
    float var = stats[256 + c] / (float)n - mu * mu;
    float gamma = bn[(L * 2 + 0) * 256 + c];
    float beta  = bn[(L * 2 + 1) * 256 + c];
    float sc = gamma * rsqrtf(var + 1e-5f);
    float sh = beta - mu * sc;
    for (int r = blockIdx.x; r < n; r += gridDim.x) {
        size_t idx = (size_t)r * 256 + c;
        float v = sc * x[idx] + sh;
        v = use_tanh ? tanhf(v) : (v > 0.f ? v : 0.01f * v);
        y[idx] = v;
        __nv_bfloat16 h = __float2bfloat16_rn(v);
        yh[idx] = h;
        yl[idx] = __float2bfloat16_rn(v - __bfloat162float(h));
    }
}

// ---------------- static stream/event setup (pre-checkpoint) ----------------
namespace {
struct StreamInit {
    cudaStream_t s2 = 0;
    cudaEvent_t ev[32];
    bool ok = false;
    StreamInit() {
        if (cudaStreamCreateWithFlags(&s2, cudaStreamNonBlocking) != cudaSuccess) return;
        for (int i = 0; i < 32; i++)
            if (cudaEventCreateWithFlags(&ev[i], cudaEventDisableTiming) != cudaSuccess)
                return;
        k_noop<<<1, 32>>>();
        k_noop<<<1, 32, 0, s2>>>();
        for (int i = 0; i < 32; i++) cudaEventRecord(ev[i], (i & 1) ? s2 : 0);
        if (cudaDeviceSynchronize() != cudaSuccess) return;
        if (cudaGetLastError() != cudaSuccess) return;
        ok = true;
    }
};
StreamInit g_si;
}

// ---------------- host orchestration ----------------
static inline int wgrid(int nwarp) { return (nwarp * 32 + 255) / 256; }

struct Ptrs {
    float *hu, *hi, *hsu, *hsi, *nu, *ni;
    float *el_u, *el_i, *er_u, *er_i, *Vui, *Viu, *stats_i, *stats_u;
    __nv_bfloat16 *WHu, *WLu, *WHi, *WLi, *Auh, *Aul, *Aih, *Ail;
    int *rp_i, *rp_u, *srcs_i, *srcs_u, *cur_i, *cur_u, *part;
};

static void get_ptrs(Ptrs& p) {
    cudaGetSymbolAddress((void**)&p.hu, g_hu);
    cudaGetSymbolAddress((void**)&p.hi, g_hi);
    cudaGetSymbolAddress((void**)&p.hsu, g_hsu);
    cudaGetSymbolAddress((void**)&p.hsi, g_hsi);
    cudaGetSymbolAddress((void**)&p.nu, g_nu);
    cudaGetSymbolAddress((void**)&p.ni, g_ni);
    cudaGetSymbolAddress((void**)&p.el_u, g_el_u);
    cudaGetSymbolAddress((void**)&p.el_i, g_el_i);
    cudaGetSymbolAddress((void**)&p.er_u, g_er_u);
    cudaGetSymbolAddress((void**)&p.er_i, g_er_i);
    cudaGetSymbolAddress((void**)&p.Vui, g_Vui);
    cudaGetSymbolAddress((void**)&p.Viu, g_Viu);
    cudaGetSymbolAddress((void**)&p.stats_i, g_stats_i);
    cudaGetSymbolAddress((void**)&p.stats_u, g_stats_u);
    cudaGetSymbolAddress((void**)&p.WHu, g_WHu);
    cudaGetSymbolAddress((void**)&p.WLu, g_WLu);
    cudaGetSymbolAddress((void**)&p.WHi, g_WHi);
    cudaGetSymbolAddress((void**)&p.WLi, g_WLi);
    cudaGetSymbolAddress((void**)&p.Auh, g_Auh);
    cudaGetSymbolAddress((void**)&p.Aul, g_Aul);
    cudaGetSymbolAddress((void**)&p.Aih, g_Aih);
    cudaGetSymbolAddress((void**)&p.Ail, g_Ail);
    cudaGetSymbolAddress((void**)&p.rp_i, g_rp_i);
    cudaGetSymbolAddress((void**)&p.rp_u, g_rp_u);
    cudaGetSymbolAddress((void**)&p.srcs_i, g_srcs_i);
    cudaGetSymbolAddress((void**)&p.srcs_u, g_srcs_u);
    cudaGetSymbolAddress((void**)&p.cur_i, g_cur_i);
    cudaGetSymbolAddress((void**)&p.cur_u, g_cur_u);
    cudaGetSymbolAddress((void**)&p.part, g_part);
}

#define SMEM256 (2 * (2 * 128 * 80 + 2 * 32 * (256 * 2 + 16)))
#define SMEM128 (2 * (2 * 128 * 80 + 2 * 32 * (128 * 2 + 16)))

static const int WOFF[4] = {0, 32768, 98304, 163840};
static const int WSZ[4]  = {32768, 65536, 65536, 32768};
#define VOFF(L) ((L) * FHID * NHEAD)

static void scan(const int* cnt, int n, int* rp, int* part, cudaStream_t st) {
    int nb = (n + 1023) / 1024;
    k_scan_blk<<<nb, 1024, 0, st>>>(cnt, n, rp, part);
    k_scan_part<<<1, 64, 0, st>>>(part, nb);
    k_scan_add<<<nb, 1024, 0, st>>>(rp, part, n);
}

extern "C" void kernel_launch(void* const* d_in, const int* in_sizes, int n_in,
                              void* d_out, int out_size) {
    Ptrs p;
    get_ptrs(p);
    cudaFuncSetAttribute(k_mma_gemm<256, 64>,
                         cudaFuncAttributeMaxDynamicSharedMemorySize, SMEM256);
    cudaFuncSetAttribute(k_mma_gemm<128, 32>,
                         cudaFuncAttributeMaxDynamicSharedMemorySize, SMEM128);

    const float* x_user = (const float*)d_in[0];
    const float* x_item = (const float*)d_in[1];
    const int*   eu     = (const int*)d_in[2];
    const int*   ei     = (const int*)d_in[3];

    bool dictOrder = (in_sizes[5] < 10000);
    const float *Wui[4], *Aui[4], *Wiu[4], *Aiu[4];
    for (int L = 0; L < 4; L++) {
        if (dictOrder) {
            Wui[L] = (const float*)d_in[4 + L * 4 + 0];
            Aui[L] = (const float*)d_in[4 + L * 4 + 1];
            Wiu[L] = (const float*)d_in[4 + L * 4 + 2];
            Aiu[L] = (const float*)d_in[4 + L * 4 + 3];
        } else {
            Wui[L] = (const float*)d_in[4 + L * 4 + 0];
            Wiu[L] = (const float*)d_in[4 + L * 4 + 1];
            Aui[L] = (const float*)d_in[4 + L * 4 + 2];
            Aiu[L] = (const float*)d_in[4 + L * 4 + 3];
        }
    }
    const float* bn_u = (const float*)d_in[20];
    const float* bn_i = (const float*)d_in[21];
    float* out = (float*)d_out;

    cudaStream_t SA = 0;
    cudaStream_t SB = g_si.ok ? g_si.s2 : (cudaStream_t)0;
    bool fork = g_si.ok;
    int ec = 0;
    auto REC = [&](cudaStream_t st) -> int {
        if (!fork) return -1;
        int i = ec++;
        cudaEventRecord(g_si.ev[i], st);
        return i;
    };
    auto WAITE = [&](cudaStream_t st, int i) {
        if (fork && i >= 0) cudaStreamWaitEvent(st, g_si.ev[i], 0);
    };

    // ---- capture-legal fork ----
    int evFork = REC(SA);
    WAITE(SB, evFork);

    // ---- pre-split weights + collapse V for all layers ----
    for (int L = 0; L < 4; L++) {
        int fin = (L == 0) ? FIN0 : FHID;
        int F = (L == 3) ? 128 : 256;
        int dh = (L == 3) ? 32 : 64;
        k_split<<<(WSZ[L] + 255) / 256, 256, 0, SA>>>(Wui[L], p.WHu + WOFF[L],
                                                      p.WLu + WOFF[L], WSZ[L]);
        k_collapseV<<<(fin * 4 + 255) / 256, 256, 0, SA>>>(Wui[L], Aui[L],
                                                           p.Vui + VOFF(L), fin, F, dh);
        k_split<<<(WSZ[L] + 255) / 256, 256, 0, SB>>>(Wiu[L], p.WHi + WOFF[L],
                                                      p.WLi + WOFF[L], WSZ[L]);
        k_collapseV<<<(fin * 4 + 255) / 256, 256, 0, SB>>>(Wiu[L], Aiu[L],
                                                           p.Viu + VOFF(L), fin, F, dh);
    }

    // ---- layer-0 input splits ----
    k_split<<<(NUSR * FIN0 + 255) / 256, 256, 0, SA>>>(x_user, p.Auh, p.Aul, NUSR * FIN0);
    k_split<<<(NITM * FIN0 + 255) / 256, 256, 0, SB>>>(x_item, p.Aih, p.Ail, NITM * FIN0);

    // ---- CSR build on SB ----
    k_zeroi<<<(NUSR + 255) / 256, 256, 0, SB>>>(p.cur_u, NUSR);
    k_zeroi<<<(NITM + 255) / 256, 256, 0, SB>>>(p.cur_i, NITM);
    k_count<<<(NEDG + 255) / 256, 256, 0, SB>>>(eu, ei, p.cur_u, p.cur_i);
    scan(p.cur_i, NITM, p.rp_i, p.part, SB);
    scan(p.cur_u, NUSR, p.rp_u, p.part, SB);
    k_copyi<<<(NITM + 255) / 256, 256, 0, SB>>>(p.rp_i, p.cur_i, NITM);
    k_copyi<<<(NUSR + 255) / 256, 256, 0, SB>>>(p.rp_u, p.cur_u, NUSR);
    k_scatter<<<(NEDG + 255) / 256, 256, 0, SB>>>(eu, ei, p.cur_u, p.cur_i,
                                                  p.srcs_u, p.srcs_i);
    int evCSR = REC(SB);

    const float* cu = x_user;
    const float* ci = x_item;
    int fin = FIN0;
    for (int L = 0; L < 4; L++) {
        int F = (L == 3) ? 128 : 256;
        float* outi = (L == 3) ? (out + (size_t)NUSR * 128) : p.ni;
        float* outu = (L == 3) ? out : p.nu;
        int gbU = (NUSR + 127) / 128, gbI = (NITM + 127) / 128;

        // ---- SA: user GEMM (+el_u), er_i ----
        if (F == 256)
            k_mma_gemm<256, 64><<<gbU, 512, SMEM256, SA>>>(p.Auh, p.Aul,
                p.WHu + WOFF[L], p.WLu + WOFF[L], Aui[L], p.hsu, p.el_u, NUSR, fin);
        else
            k_mma_gemm<128, 32><<<gbU, 256, SMEM128, SA>>>(p.Auh, p.Aul,
                p.WHu + WOFF[L], p.WLu + WOFF[L], Aui[L], p.hsu, p.el_u, NUSR, fin);
        int evAg = REC(SA);
        k_er<<<wgrid(NITM), 256, 0, SA>>>(ci, (const float4*)(p.Vui + VOFF(L)),
                                          p.er_i, NITM, fin);

        // ---- SB: item GEMM (+el_i), er_u ----
        if (F == 256)
            k_mma_gemm<256, 64><<<gbI, 512, SMEM256, SB>>>(p.Aih, p.Ail,
                p.WHi + WOFF[L], p.WLi + WOFF[L], Aiu[L], p.hsi, p.el_i, NITM, fin);
        else
            k_mma_gemm<128, 32><<<gbI, 256, SMEM128, SB>>>(p.Aih, p.Ail,
                p.WHi + WOFF[L], p.WLi + WOFF[L], Aiu[L], p.hsi, p.el_i, NITM, fin);
        int evBg = REC(SB);
        k_er<<<wgrid(NUSR), 256, 0, SB>>>(cu, (const float4*)(p.Viu + VOFF(L)),
                                          p.er_u, NUSR, fin);

        // ---- edges: item-dst on SA (needs el_u [SA], er_i [SA], hsu [SA], CSR) ----
        if (L == 0) WAITE(SA, evCSR);
        if (F == 256) {
            k_edge256<<<wgrid(NITM), 256, 0, SA>>>(p.rp_i, p.srcs_i,
                (const float4*)p.el_u, (const float4*)p.er_i, p.hsu, outi,
                (L < 3) ? p.stats_i : nullptr, NITM);
            k_edge256<<<wgrid(NUSR), 256, 0, SB>>>(p.rp_u, p.srcs_u,
                (const float4*)p.el_i, (const float4*)p.er_u, p.hsi, outu,
                (L < 3) ? p.stats_u : nullptr, NUSR);
        } else {
            k_edge128<<<wgrid(NITM), 256, 0, SA>>>(p.rp_i, p.srcs_i,
                (const float4*)p.el_u, (const float4*)p.er_i, p.hsu, outi, NITM);
            k_edge128<<<wgrid(NUSR), 256, 0, SB>>>(p.rp_u, p.srcs_u,
                (const float4*)p.el_i, (const float4*)p.er_u, p.hsi, outu, NUSR);
        }
        // NOTE: edge_i on SA reads el_i? No — edge_i (item dst) uses el_u + er_i,
        // both produced on SA. edge_u on SB uses el_i + er_u, both produced on SB.

        if (L < 3) {
            // BN item on SA (stats_i zeroed by edge256 block 0 on SA)
            k_bnstats<<<256, 256, 0, SA>>>(p.ni, p.stats_i, NITM);
            WAITE(SA, evBg);   // bnapply writes Aih/Ail read by SB's gemm this layer
            k_bnapply<<<256, 256, 0, SA>>>(p.ni, p.hi, p.Aih, p.Ail, bn_i,
                                           p.stats_i, L, NITM, (L == 2) ? 1 : 0);
            // BN user on SB (stats_u zeroed by edge256 block 0 on SB)
            k_bnstats<<<256, 256, 0, SB>>>(p.nu, p.stats_u, NUSR);
            WAITE(SB, evAg);   // bnapply writes Auh/Aul read by SA's gemm this layer
            k_bnapply<<<256, 256, 0, SB>>>(p.nu, p.hu, p.Auh, p.Aul, bn_u,
                                           p.stats_u, L, NUSR, (L == 2) ? 1 : 0);
            // layer-boundary cross joins:
            // next SA gemm reads Auh/Aul (made on SB); next SA er_i reads hi (made on SA, ok)
            // next SB gemm reads Aih/Ail (made on SA); next SB er_u reads hu (made on SB, ok)
            int evAe = REC(SA);
            int evBe = REC(SB);
            WAITE(SA, evBe);
            WAITE(SB, evAe);
            cu = p.hu;
            ci = p.hi;
            fin = FHID;
        } else {
            int evBf = REC(SB);
            WAITE(SA, evBf);
        }
    }
    (void)n_in; (void)out_size;
}

// round 9
// speedup vs baseline: 1.3160x; 1.2556x over previous
#include <cuda_runtime.h>
#include <cuda_bf16.h>
#include <math.h>
#include <stddef.h>
#include <stdint.h>

// ---------------- problem constants ----------------
#define NUSR 50000
#define NITM 20000
#define NEDG 400000
#define FIN0 128
#define FHID 256
#define NHEAD 4

// ---------------- device scratch (no allocs allowed) ----------------
__device__ float g_hu [(size_t)NUSR * FHID];
__device__ float g_hi [(size_t)NITM * FHID];
__device__ float g_hsu[(size_t)NUSR * FHID];
__device__ float g_hsi[(size_t)NITM * FHID];
__device__ float g_nu [(size_t)NUSR * FHID];
__device__ float g_ni [(size_t)NITM * FHID];
__device__ float g_el_u[NUSR * 4];
__device__ float g_el_i[NITM * 4];
__device__ int   g_rp_i[NITM + 1];
__device__ int   g_rp_u[NUSR + 1];
__device__ int   g_srcs_i[NEDG];
__device__ int   g_srcs_u[NEDG];
__device__ int   g_cur_i[NITM];
__device__ int   g_cur_u[NUSR];
__device__ float g_Vui[4 * FHID * NHEAD];
__device__ float g_Viu[4 * FHID * NHEAD];
__device__ float g_stats_i[3 * 512];   // per-layer BN stats (sum | sumsq)
__device__ float g_stats_u[3 * 512];
__device__ int   g_part[64];
__device__ __nv_bfloat16 g_WHu[196608];
__device__ __nv_bfloat16 g_WLu[196608];
__device__ __nv_bfloat16 g_WHi[196608];
__device__ __nv_bfloat16 g_WLi[196608];
__device__ __nv_bfloat16 g_Auh[(size_t)NUSR * FHID];
__device__ __nv_bfloat16 g_Aul[(size_t)NUSR * FHID];
__device__ __nv_bfloat16 g_Aih[(size_t)NITM * FHID];
__device__ __nv_bfloat16 g_Ail[(size_t)NITM * FHID];

// ---------------- PTX helpers (baseline features only) ----------------
__device__ __forceinline__ uint32_t smem_u32(const void* p) {
    uint32_t a;
    asm("{ .reg .u64 t; cvta.to.shared.u64 t, %1; cvt.u32.u64 %0, t; }"
        : "=r"(a) : "l"(p));
    return a;
}
__device__ __forceinline__ void ldsm4(uint32_t* r, uint32_t addr) {
    asm volatile("ldmatrix.sync.aligned.m8n8.x4.shared.b16 {%0,%1,%2,%3}, [%4];"
        : "=r"(r[0]), "=r"(r[1]), "=r"(r[2]), "=r"(r[3]) : "r"(addr));
}
__device__ __forceinline__ void ldsm4t(uint32_t* r, uint32_t addr) {
    asm volatile("ldmatrix.sync.aligned.m8n8.x4.trans.shared.b16 {%0,%1,%2,%3}, [%4];"
        : "=r"(r[0]), "=r"(r[1]), "=r"(r[2]), "=r"(r[3]) : "r"(addr));
}
__device__ __forceinline__ void mma16816(float* c, const uint32_t* a,
                                         uint32_t b0, uint32_t b1) {
    asm volatile(
        "mma.sync.aligned.m16n8k16.row.col.f32.bf16.bf16.f32 "
        "{%0,%1,%2,%3}, {%4,%5,%6,%7}, {%8,%9}, {%0,%1,%2,%3};"
        : "+f"(c[0]), "+f"(c[1]), "+f"(c[2]), "+f"(c[3])
        : "r"(a[0]), "r"(a[1]), "r"(a[2]), "r"(a[3]), "r"(b0), "r"(b1));
}
#define CPA16(dst, src) \
    asm volatile("cp.async.cg.shared.global [%0], [%1], 16;" \
                 :: "r"(dst), "l"(src))
#define CP_COMMIT() asm volatile("cp.async.commit_group;")
#define CP_WAIT1()  asm volatile("cp.async.wait_group 1;" ::: "memory")
#define CP_WAIT0()  asm volatile("cp.async.wait_group 0;" ::: "memory")

// ---------------- tiny utility kernels ----------------
__global__ void k_noop() {}
__global__ void k_zeroi(int* p, int n) {
    int i = blockIdx.x * blockDim.x + threadIdx.x;
    if (i < n) p[i] = 0;
}
__global__ void k_zerof(float* p, int n) {
    int i = blockIdx.x * blockDim.x + threadIdx.x;
    if (i < n) p[i] = 0.f;
}
__global__ void k_copyi(const int* __restrict__ a, int* __restrict__ b, int n) {
    int i = blockIdx.x * blockDim.x + threadIdx.x;
    if (i < n) b[i] = a[i];
}

// ---------------- CSR construction ----------------
__global__ void k_count(const int* __restrict__ eu, const int* __restrict__ ei,
                        int* cu, int* ci) {
    int k = blockIdx.x * blockDim.x + threadIdx.x;
    if (k < NEDG) {
        atomicAdd(&ci[ei[k]], 1);
        atomicAdd(&cu[eu[k]], 1);
    }
}
__global__ void k_scan_blk(const int* __restrict__ cnt, int n,
                           int* __restrict__ rp, int* __restrict__ part) {
    __shared__ int ws[32];
    int tid = threadIdx.x;
    int i = blockIdx.x * 1024 + tid;
    int v = (i < n) ? cnt[i] : 0;
    int lane = tid & 31, w = tid >> 5;
    int x = v;
    #pragma unroll
    for (int o = 1; o < 32; o <<= 1) {
        int y = __shfl_up_sync(0xffffffffu, x, o);
        if (lane >= o) x += y;
    }
    if (lane == 31) ws[w] = x;
    __syncthreads();
    if (w == 0) {
        int t = ws[lane];
        #pragma unroll
        for (int o = 1; o < 32; o <<= 1) {
            int y = __shfl_up_sync(0xffffffffu, t, o);
            if (lane >= o) t += y;
        }
        ws[lane] = t;
    }
    __syncthreads();
    int incl = x + (w > 0 ? ws[w - 1] : 0);
    if (i < n) rp[i + 1] = incl;
    if (tid == 1023) part[blockIdx.x] = incl;
}
__global__ void k_scan_part(int* part, int nb) {
    __shared__ int w0sum;
    int tid = threadIdx.x;
    int v = (tid < nb) ? part[tid] : 0;
    int lane = tid & 31, w = tid >> 5;
    int x = v;
    #pragma unroll
    for (int o = 1; o < 32; o <<= 1) {
        int y = __shfl_up_sync(0xffffffffu, x, o);
        if (lane >= o) x += y;
    }
    if (w == 0 && lane == 31) w0sum = x;
    __syncthreads();
    int incl = x + (w ? w0sum : 0);
    if (tid < nb) part[tid] = incl - v;
}
__global__ void k_scan_add(int* __restrict__ rp, const int* __restrict__ part, int n) {
    int i = blockIdx.x * 1024 + threadIdx.x;
    if (i < n) rp[i + 1] += part[blockIdx.x];
    if (i == 0) rp[0] = 0;
}
__global__ void k_scatter(const int* __restrict__ eu, const int* __restrict__ ei,
                          int* cu, int* ci,
                          int* __restrict__ su, int* __restrict__ si) {
    int k = blockIdx.x * blockDim.x + threadIdx.x;
    if (k < NEDG) {
        int u = eu[k], it = ei[k];
        int p = atomicAdd(&ci[it], 1);
        si[p] = u;
        int q = atomicAdd(&cu[u], 1);
        su[q] = it;
    }
}

// ---------------- elementwise fp32 -> bf16 hi/lo split ----------------
__global__ void k_split(const float* __restrict__ X, __nv_bfloat16* __restrict__ xh,
                        __nv_bfloat16* __restrict__ xl, int total) {
    int id = blockIdx.x * blockDim.x + threadIdx.x;
    if (id >= total) return;
    float v = X[id];
    __nv_bfloat16 h = __float2bfloat16_rn(v);
    xh[id] = h;
    xl[id] = __float2bfloat16_rn(v - __bfloat162float(h));
}

// ---------------- tensor-core GEMM + fused el epilogue ----------------
template <int BN, int DH>
__global__ void __launch_bounds__((BN == 256) ? 512 : 256, 1)
k_mma_gemm(const __nv_bfloat16* __restrict__ Ah, const __nv_bfloat16* __restrict__ Al,
           const __nv_bfloat16* __restrict__ Bh, const __nv_bfloat16* __restrict__ Bl,
           const float* __restrict__ attA,
           float* __restrict__ C, float* __restrict__ el, int M, int K) {
    constexpr int NT = (BN == 256) ? 512 : 256;
    constexpr int SBSTR = BN * 2 + 16;
    constexpr int ASZ = 128 * 80;
    constexpr int BOFF = 2 * ASZ;
    constexpr int BSZ = 32 * SBSTR;
    constexpr int STAGE = BOFF + 2 * BSZ;
    constexpr int NBC = 32 * (BN / 8);

    extern __shared__ char smem[];
    uint32_t sb = smem_u32(smem);
    int tid = threadIdx.x;
    int wid = tid >> 5, lane = tid & 31;
    int wm = wid & 3, wn = wid >> 2;
    int bm = blockIdx.x * 128;

    float acc[2][8][4];
    #pragma unroll
    for (int i = 0; i < 2; i++)
        #pragma unroll
        for (int j = 0; j < 8; j++)
            #pragma unroll
            for (int q = 0; q < 4; q++) acc[i][j][q] = 0.f;

    int nch = K >> 5;

    auto load_stage = [&](int st, int kc) {
        uint32_t sbase = sb + st * STAGE;
        int k0 = kc << 5;
        #pragma unroll
        for (int c = tid; c < 512; c += NT) {
            int row = c >> 2, q = c & 3;
            int gr = bm + row;
            gr = gr < M ? gr : M - 1;
            size_t gi = (size_t)gr * K + k0 + q * 8;
            uint32_t d = sbase + row * 80 + q * 16;
            CPA16(d, Ah + gi);
            CPA16(d + ASZ, Al + gi);
        }
        #pragma unroll
        for (int c = tid; c < NBC; c += NT) {
            int k = c / (BN / 8), seg = c % (BN / 8);
            size_t gi = (size_t)(k0 + k) * BN + seg * 8;
            uint32_t d = sbase + BOFF + k * SBSTR + seg * 16;
            CPA16(d, Bh + gi);
            CPA16(d + BSZ, Bl + gi);
        }
        CP_COMMIT();
    };

    load_stage(0, 0);
    for (int kc = 0; kc < nch; kc++) {
        int cur = kc & 1;
        if (kc + 1 < nch) {
            load_stage(1 - cur, kc + 1);
            CP_WAIT1();
        } else {
            CP_WAIT0();
        }
        __syncthreads();
        uint32_t abase = sb + cur * STAGE;
        #pragma unroll
        for (int s = 0; s < 2; s++) {
            uint32_t Af[2][4], Alf[2][4];
            #pragma unroll
            for (int mt = 0; mt < 2; mt++) {
                uint32_t ad = abase +
                    (uint32_t)(wm * 32 + mt * 16 + (lane & 15)) * 80 +
                    s * 32 + (lane >> 4) * 16;
                ldsm4(Af[mt], ad);
                ldsm4(Alf[mt], ad + ASZ);
            }
            #pragma unroll
            for (int np = 0; np < 4; np++) {
                int g = lane >> 3, r = lane & 7;
                int kk = s * 16 + (g & 1) * 8 + r;
                int nn = wn * 64 + np * 16 + (g >> 1) * 8;
                uint32_t bd = abase + BOFF + (uint32_t)kk * SBSTR + nn * 2;
                uint32_t bh4[4], bl4[4];
                ldsm4t(bh4, bd);
                ldsm4t(bl4, bd + BSZ);
                #pragma unroll
                for (int mt = 0; mt < 2; mt++)
                    #pragma unroll
                    for (int sub = 0; sub < 2; sub++) {
                        float* a = acc[mt][np * 2 + sub];
                        mma16816(a, Af[mt], bh4[2 * sub], bh4[2 * sub + 1]);
                        mma16816(a, Af[mt], bl4[2 * sub], bl4[2 * sub + 1]);
                        mma16816(a, Alf[mt], bh4[2 * sub], bh4[2 * sub + 1]);
                    }
            }
        }
        __syncthreads();
    }

    constexpr int HPW = 64 / DH;
    int grp = lane >> 2, tq = lane & 3;
    #pragma unroll
    for (int mt = 0; mt < 2; mt++) {
        int r0 = bm + wm * 32 + mt * 16 + grp;
        int r1 = r0 + 8;
        #pragma unroll
        for (int nt = 0; nt < 8; nt++) {
            int col = wn * 64 + nt * 8 + tq * 2;
            if (r0 < M)
                *(float2*)(C + (size_t)r0 * BN + col) =
                    make_float2(acc[mt][nt][0], acc[mt][nt][1]);
            if (r1 < M)
                *(float2*)(C + (size_t)r1 * BN + col) =
                    make_float2(acc[mt][nt][2], acc[mt][nt][3]);
        }
        float s0[HPW], s1[HPW];
        #pragma unroll
        for (int p = 0; p < HPW; p++) { s0[p] = 0.f; s1[p] = 0.f; }
        #pragma unroll
        for (int nt = 0; nt < 8; nt++) {
            int part = (nt * 8) / DH;
            int col = wn * 64 + nt * 8 + tq * 2;
            float c0 = attA[col], c1 = attA[col + 1];
            s0[part] += c0 * acc[mt][nt][0] + c1 * acc[mt][nt][1];
            s1[part] += c0 * acc[mt][nt][2] + c1 * acc[mt][nt][3];
        }
        #pragma unroll
        for (int p = 0; p < HPW; p++) {
            s0[p] += __shfl_xor_sync(0xffffffffu, s0[p], 1);
            s0[p] += __shfl_xor_sync(0xffffffffu, s0[p], 2);
            s1[p] += __shfl_xor_sync(0xffffffffu, s1[p], 1);
            s1[p] += __shfl_xor_sync(0xffffffffu, s1[p], 2);
            if (tq == 0) {
                int h = wn * HPW + p;
                if (r0 < M) el[r0 * 4 + h] = s0[p];
                if (r1 < M) el[r1 * 4 + h] = s1[p];
            }
        }
    }
}

// ---------------- V[k,h] = sum_d W[k, h*dh+d] * A1[h,d] ----------------
__global__ void k_collapseV(const float* __restrict__ W, const float* __restrict__ A,
                            float* __restrict__ V, int fin, int F, int dh) {
    int t = blockIdx.x * blockDim.x + threadIdx.x;
    if (t >= fin * NHEAD) return;
    int k = t >> 2, h = t & 3;
    const float* A1 = A + NHEAD * dh;
    float s = 0.f;
    for (int d = 0; d < dh; d++)
        s += W[(size_t)k * F + h * dh + d] * A1[h * dh + d];
    V[t] = s;
}

__device__ __forceinline__ float lrelu(float x, float s) { return x > 0.f ? x : s * x; }

// ---- fused edge kernel, F=256: er (from cdst·V) + 1-pass softmax-agg + BN stats ----
// grid-stride over dsts; per-lane register stats, one smem+global flush at end.
__global__ void __launch_bounds__(256)
k_edge256s(const int* __restrict__ rp, const int* __restrict__ srcs,
           const float4* __restrict__ el4, const float4* __restrict__ V4,
           const float* __restrict__ cdst, const float* __restrict__ hs,
           float* __restrict__ out, float* __restrict__ stats,
           int ndst, int fin) {
    __shared__ float s_st[512];
    int tid = threadIdx.x;
    for (int i = tid; i < 512; i += 256) s_st[i] = 0.f;
    __syncthreads();
    int lane = tid & 31, wloc = tid >> 5;
    bool loHalf = lane < 16;
    float sm0[4] = {0.f, 0.f, 0.f, 0.f}, sq0[4] = {0.f, 0.f, 0.f, 0.f};
    float sm1[4] = {0.f, 0.f, 0.f, 0.f}, sq1[4] = {0.f, 0.f, 0.f, 0.f};

    for (int w = blockIdx.x * 8 + wloc; w < ndst; w += gridDim.x * 8) {
        // er from destination row
        const float* c = cdst + (size_t)w * fin;
        float a0 = 0.f, a1 = 0.f, a2 = 0.f, a3 = 0.f;
        for (int k = lane; k < fin; k += 32) {
            float xv = c[k];
            float4 v = V4[k];
            a0 += xv * v.x; a1 += xv * v.y; a2 += xv * v.z; a3 += xv * v.w;
        }
        #pragma unroll
        for (int o = 16; o; o >>= 1) {
            a0 += __shfl_xor_sync(0xffffffffu, a0, o);
            a1 += __shfl_xor_sync(0xffffffffu, a1, o);
            a2 += __shfl_xor_sync(0xffffffffu, a2, o);
            a3 += __shfl_xor_sync(0xffffffffu, a3, o);
        }
        float erA = loHalf ? a0 : a1, erB = loHalf ? a2 : a3;

        int s0 = rp[w], s1 = rp[w + 1];
        float4 o0 = make_float4(0.f, 0.f, 0.f, 0.f);
        float4 o1 = make_float4(0.f, 0.f, 0.f, 0.f);
        if (s0 != s1) {
            float4 acc0 = make_float4(0.f, 0.f, 0.f, 0.f);
            float4 acc1 = make_float4(0.f, 0.f, 0.f, 0.f);
            float zA = 0.f, zB = 0.f;
            for (int j = s0; j < s1; j++) {
                int s = srcs[j];
                float4 e = el4[s];
                float eA = loHalf ? e.x : e.y, eB = loHalf ? e.z : e.w;
                float aA = expf(lrelu(eA + erA, 0.2f));
                float aB = expf(lrelu(eB + erB, 0.2f));
                const float4* row = (const float4*)(hs + (size_t)s * 256);
                float4 v0 = row[lane];
                float4 v1 = row[lane + 32];
                acc0.x += aA * v0.x; acc0.y += aA * v0.y;
                acc0.z += aA * v0.z; acc0.w += aA * v0.w;
                acc1.x += aB * v1.x; acc1.y += aB * v1.y;
                acc1.z += aB * v1.z; acc1.w += aB * v1.w;
                zA += aA; zB += aB;
            }
            float iA = 1.f / zA, iB = 1.f / zB;
            o0 = make_float4(acc0.x * iA, acc0.y * iA, acc0.z * iA, acc0.w * iA);
            o1 = make_float4(acc1.x * iB, acc1.y * iB, acc1.z * iB, acc1.w * iB);
        }
        float4* op = (float4*)(out + (size_t)w * 256);
        op[lane] = o0;
        op[lane + 32] = o1;
        // accumulate BN stats in registers (cols lane*4+q and 128+lane*4+q)
        sm0[0] += o0.x; sq0[0] += o0.x * o0.x;
        sm0[1] += o0.y; sq0[1] += o0.y * o0.y;
        sm0[2] += o0.z; sq0[2] += o0.z * o0.z;
        sm0[3] += o0.w; sq0[3] += o0.w * o0.w;
        sm1[0] += o1.x; sq1[0] += o1.x * o1.x;
        sm1[1] += o1.y; sq1[1] += o1.y * o1.y;
        sm1[2] += o1.z; sq1[2] += o1.z * o1.z;
        sm1[3] += o1.w; sq1[3] += o1.w * o1.w;
    }
    // flush: smem accumulate (sum in [0,256), sumsq in [256,512))
    #pragma unroll
    for (int q = 0; q < 4; q++) {
        atomicAdd(&s_st[lane * 4 + q], sm0[q]);
        atomicAdd(&s_st[256 + lane * 4 + q], sq0[q]);
        atomicAdd(&s_st[128 + lane * 4 + q], sm1[q]);
        atomicAdd(&s_st[256 + 128 + lane * 4 + q], sq1[q]);
    }
    __syncthreads();
    for (int i = tid; i < 512; i += 256)
        atomicAdd(&stats[i], s_st[i]);
}

// ---- fused edge kernel, F=128 (dh=32): er + 1-pass softmax-agg, no stats ----
__global__ void k_edge128f(const int* __restrict__ rp, const int* __restrict__ srcs,
                           const float4* __restrict__ el4, const float4* __restrict__ V4,
                           const float* __restrict__ cdst, const float* __restrict__ hs,
                           float* __restrict__ out, int ndst, int fin) {
    int w = (blockIdx.x * blockDim.x + threadIdx.x) >> 5;
    int lane = threadIdx.x & 31;
    if (w >= ndst) return;
    // er
    const float* c = cdst + (size_t)w * fin;
    float a0 = 0.f, a1 = 0.f, a2 = 0.f, a3 = 0.f;
    for (int k = lane; k < fin; k += 32) {
        float xv = c[k];
        float4 v = V4[k];
        a0 += xv * v.x; a1 += xv * v.y; a2 += xv * v.z; a3 += xv * v.w;
    }
    #pragma unroll
    for (int o = 16; o; o >>= 1) {
        a0 += __shfl_xor_sync(0xffffffffu, a0, o);
        a1 += __shfl_xor_sync(0xffffffffu, a1, o);
        a2 += __shfl_xor_sync(0xffffffffu, a2, o);
        a3 += __shfl_xor_sync(0xffffffffu, a3, o);
    }
    int hsel = lane >> 3;
    float erS = (hsel == 0) ? a0 : (hsel == 1) ? a1 : (hsel == 2) ? a2 : a3;

    int s0 = rp[w], s1 = rp[w + 1];
    float4* o = (float4*)(out + (size_t)w * 128);
    if (s0 == s1) {
        o[lane] = make_float4(0.f, 0.f, 0.f, 0.f);
        return;
    }
    float4 acc = make_float4(0.f, 0.f, 0.f, 0.f);
    float z = 0.f;
    for (int j = s0; j < s1; j++) {
        int s = srcs[j];
        float4 e = el4[s];
        float eS = (hsel == 0) ? e.x : (hsel == 1) ? e.y : (hsel == 2) ? e.z : e.w;
        float a = expf(lrelu(eS + erS, 0.2f));
        const float4* row = (const float4*)(hs + (size_t)s * 128);
        float4 v = row[lane];
        acc.x += a * v.x; acc.y += a * v.y; acc.z += a * v.z; acc.w += a * v.w;
        z += a;
    }
    float iz = 1.f / z;
    o[lane] = make_float4(acc.x * iz, acc.y * iz, acc.z * iz, acc.w * iz);
}

// ---------------- BatchNorm apply (+act +bf16 split for next GEMM) -------------
__global__ void k_bnapply(const float* __restrict__ x, float* __restrict__ y,
                          __nv_bfloat16* __restrict__ yh, __nv_bfloat16* __restrict__ yl,
                          const float* __restrict__ bn, const float* __restrict__ stats,
                          int L, int n, int use_tanh) {
    int c = threadIdx.x;
    float mu = stats[c] / (float)n;
    float var = stats[256 + c] / (float)n - mu * mu;
    float gamma = bn[(L * 2 + 0) * 256 + c];
    float beta  = bn[(L * 2 + 1) * 256 + c];
    float sc = gamma * rsqrtf(var + 1e-5f);
    float sh = beta - mu * sc;
    for (int r = blockIdx.x; r < n; r += gridDim.x) {
        size_t idx = (size_t)r * 256 + c;
        float v = sc * x[idx] + sh;
        v = use_tanh ? tanhf(v) : (v > 0.f ? v : 0.01f * v);
        y[idx] = v;
        __nv_bfloat16 h = __float2bfloat16_rn(v);
        yh[idx] = h;
        yl[idx] = __float2bfloat16_rn(v - __bfloat162float(h));
    }
}

// ---------------- static stream/event setup (pre-checkpoint) ----------------
namespace {
struct StreamInit {
    cudaStream_t s2 = 0;
    cudaEvent_t ev[32];
    bool ok = false;
    StreamInit() {
        if (cudaStreamCreateWithFlags(&s2, cudaStreamNonBlocking) != cudaSuccess) return;
        for (int i = 0; i < 32; i++)
            if (cudaEventCreateWithFlags(&ev[i], cudaEventDisableTiming) != cudaSuccess)
                return;
        k_noop<<<1, 32>>>();
        k_noop<<<1, 32, 0, s2>>>();
        for (int i = 0; i < 32; i++) cudaEventRecord(ev[i], (i & 1) ? s2 : 0);
        if (cudaDeviceSynchronize() != cudaSuccess) return;
        if (cudaGetLastError() != cudaSuccess) return;
        ok = true;
    }
};
StreamInit g_si;
}

// ---------------- host orchestration ----------------
static inline int wgrid(int nwarp) { return (nwarp * 32 + 255) / 256; }

struct Ptrs {
    float *hu, *hi, *hsu, *hsi, *nu, *ni;
    float *el_u, *el_i, *Vui, *Viu, *stats_i, *stats_u;
    __nv_bfloat16 *WHu, *WLu, *WHi, *WLi, *Auh, *Aul, *Aih, *Ail;
    int *rp_i, *rp_u, *srcs_i, *srcs_u, *cur_i, *cur_u, *part;
};

static void get_ptrs(Ptrs& p) {
    cudaGetSymbolAddress((void**)&p.hu, g_hu);
    cudaGetSymbolAddress((void**)&p.hi, g_hi);
    cudaGetSymbolAddress((void**)&p.hsu, g_hsu);
    cudaGetSymbolAddress((void**)&p.hsi, g_hsi);
    cudaGetSymbolAddress((void**)&p.nu, g_nu);
    cudaGetSymbolAddress((void**)&p.ni, g_ni);
    cudaGetSymbolAddress((void**)&p.el_u, g_el_u);
    cudaGetSymbolAddress((void**)&p.el_i, g_el_i);
    cudaGetSymbolAddress((void**)&p.Vui, g_Vui);
    cudaGetSymbolAddress((void**)&p.Viu, g_Viu);
    cudaGetSymbolAddress((void**)&p.stats_i, g_stats_i);
    cudaGetSymbolAddress((void**)&p.stats_u, g_stats_u);
    cudaGetSymbolAddress((void**)&p.WHu, g_WHu);
    cudaGetSymbolAddress((void**)&p.WLu, g_WLu);
    cudaGetSymbolAddress((void**)&p.WHi, g_WHi);
    cudaGetSymbolAddress((void**)&p.WLi, g_WLi);
    cudaGetSymbolAddress((void**)&p.Auh, g_Auh);
    cudaGetSymbolAddress((void**)&p.Aul, g_Aul);
    cudaGetSymbolAddress((void**)&p.Aih, g_Aih);
    cudaGetSymbolAddress((void**)&p.Ail, g_Ail);
    cudaGetSymbolAddress((void**)&p.rp_i, g_rp_i);
    cudaGetSymbolAddress((void**)&p.rp_u, g_rp_u);
    cudaGetSymbolAddress((void**)&p.srcs_i, g_srcs_i);
    cudaGetSymbolAddress((void**)&p.srcs_u, g_srcs_u);
    cudaGetSymbolAddress((void**)&p.cur_i, g_cur_i);
    cudaGetSymbolAddress((void**)&p.cur_u, g_cur_u);
    cudaGetSymbolAddress((void**)&p.part, g_part);
}

#define SMEM256 (2 * (2 * 128 * 80 + 2 * 32 * (256 * 2 + 16)))
#define SMEM128 (2 * (2 * 128 * 80 + 2 * 32 * (128 * 2 + 16)))
#define EDGE_BLOCKS 592

static const int WOFF[4] = {0, 32768, 98304, 163840};
static const int WSZ[4]  = {32768, 65536, 65536, 32768};
#define VOFF(L) ((L) * FHID * NHEAD)

static void scan(const int* cnt, int n, int* rp, int* part, cudaStream_t st) {
    int nb = (n + 1023) / 1024;
    k_scan_blk<<<nb, 1024, 0, st>>>(cnt, n, rp, part);
    k_scan_part<<<1, 64, 0, st>>>(part, nb);
    k_scan_add<<<nb, 1024, 0, st>>>(rp, part, n);
}

extern "C" void kernel_launch(void* const* d_in, const int* in_sizes, int n_in,
                              void* d_out, int out_size) {
    Ptrs p;
    get_ptrs(p);
    cudaFuncSetAttribute(k_mma_gemm<256, 64>,
                         cudaFuncAttributeMaxDynamicSharedMemorySize, SMEM256);
    cudaFuncSetAttribute(k_mma_gemm<128, 32>,
                         cudaFuncAttributeMaxDynamicSharedMemorySize, SMEM128);

    const float* x_user = (const float*)d_in[0];
    const float* x_item = (const float*)d_in[1];
    const int*   eu     = (const int*)d_in[2];
    const int*   ei     = (const int*)d_in[3];

    bool dictOrder = (in_sizes[5] < 10000);
    const float *Wui[4], *Aui[4], *Wiu[4], *Aiu[4];
    for (int L = 0; L < 4; L++) {
        if (dictOrder) {
            Wui[L] = (const float*)d_in[4 + L * 4 + 0];
            Aui[L] = (const float*)d_in[4 + L * 4 + 1];
            Wiu[L] = (const float*)d_in[4 + L * 4 + 2];
            Aiu[L] = (const float*)d_in[4 + L * 4 + 3];
        } else {
            Wui[L] = (const float*)d_in[4 + L * 4 + 0];
            Wiu[L] = (const float*)d_in[4 + L * 4 + 1];
            Aui[L] = (const float*)d_in[4 + L * 4 + 2];
            Aiu[L] = (const float*)d_in[4 + L * 4 + 3];
        }
    }
    const float* bn_u = (const float*)d_in[20];
    const float* bn_i = (const float*)d_in[21];
    float* out = (float*)d_out;

    cudaStream_t SA = 0;
    cudaStream_t SB = g_si.ok ? g_si.s2 : (cudaStream_t)0;
    bool fork = g_si.ok;
    int ec = 0;
    auto REC = [&](cudaStream_t st) -> int {
        if (!fork) return -1;
        int i = ec++;
        cudaEventRecord(g_si.ev[i], st);
        return i;
    };
    auto WAITE = [&](cudaStream_t st, int i) {
        if (fork && i >= 0) cudaStreamWaitEvent(st, g_si.ev[i], 0);
    };

    // ---- capture-legal fork ----
    int evFork = REC(SA);
    WAITE(SB, evFork);

    // ---- zero per-layer BN stats (before any edge kernel accumulates) ----
    k_zerof<<<(3 * 512 + 255) / 256, 256, 0, SA>>>(p.stats_i, 3 * 512);
    k_zerof<<<(3 * 512 + 255) / 256, 256, 0, SB>>>(p.stats_u, 3 * 512);

    // ---- pre-split weights + collapse V for all layers ----
    for (int L = 0; L < 4; L++) {
        int fin = (L == 0) ? FIN0 : FHID;
        int F = (L == 3) ? 128 : 256;
        int dh = (L == 3) ? 32 : 64;
        k_split<<<(WSZ[L] + 255) / 256, 256, 0, SA>>>(Wui[L], p.WHu + WOFF[L],
                                                      p.WLu + WOFF[L], WSZ[L]);
        k_collapseV<<<(fin * 4 + 255) / 256, 256, 0, SA>>>(Wui[L], Aui[L],
                                                           p.Vui + VOFF(L), fin, F, dh);
        k_split<<<(WSZ[L] + 255) / 256, 256, 0, SB>>>(Wiu[L], p.WHi + WOFF[L],
                                                      p.WLi + WOFF[L], WSZ[L]);
        k_collapseV<<<(fin * 4 + 255) / 256, 256, 0, SB>>>(Wiu[L], Aiu[L],
                                                           p.Viu + VOFF(L), fin, F, dh);
    }

    // ---- layer-0 input splits ----
    k_split<<<(NUSR * FIN0 + 255) / 256, 256, 0, SA>>>(x_user, p.Auh, p.Aul, NUSR * FIN0);
    k_split<<<(NITM * FIN0 + 255) / 256, 256, 0, SB>>>(x_item, p.Aih, p.Ail, NITM * FIN0);

    // ---- CSR build on SB ----
    k_zeroi<<<(NUSR + 255) / 256, 256, 0, SB>>>(p.cur_u, NUSR);
    k_zeroi<<<(NITM + 255) / 256, 256, 0, SB>>>(p.cur_i, NITM);
    k_count<<<(NEDG + 255) / 256, 256, 0, SB>>>(eu, ei, p.cur_u, p.cur_i);
    scan(p.cur_i, NITM, p.rp_i, p.part, SB);
    scan(p.cur_u, NUSR, p.rp_u, p.part, SB);
    k_copyi<<<(NITM + 255) / 256, 256, 0, SB>>>(p.rp_i, p.cur_i, NITM);
    k_copyi<<<(NUSR + 255) / 256, 256, 0, SB>>>(p.rp_u, p.cur_u, NUSR);
    k_scatter<<<(NEDG + 255) / 256, 256, 0, SB>>>(eu, ei, p.cur_u, p.cur_i,
                                                  p.srcs_u, p.srcs_i);
    int evCSR = REC(SB);

    const float* cu = x_user;
    const float* ci = x_item;
    int fin = FIN0;
    for (int L = 0; L < 4; L++) {
        int F = (L == 3) ? 128 : 256;
        float* outi = (L == 3) ? (out + (size_t)NUSR * 128) : p.ni;
        float* outu = (L == 3) ? out : p.nu;
        int gbU = (NUSR + 127) / 128, gbI = (NITM + 127) / 128;

        // ---- SA: user GEMM (+el_u) ----
        if (F == 256)
            k_mma_gemm<256, 64><<<gbU, 512, SMEM256, SA>>>(p.Auh, p.Aul,
                p.WHu + WOFF[L], p.WLu + WOFF[L], Aui[L], p.hsu, p.el_u, NUSR, fin);
        else
            k_mma_gemm<128, 32><<<gbU, 256, SMEM128, SA>>>(p.Auh, p.Aul,
                p.WHu + WOFF[L], p.WLu + WOFF[L], Aui[L], p.hsu, p.el_u, NUSR, fin);
        int evAg = REC(SA);

        // ---- SB: item GEMM (+el_i) ----
        if (F == 256)
            k_mma_gemm<256, 64><<<gbI, 512, SMEM256, SB>>>(p.Aih, p.Ail,
                p.WHi + WOFF[L], p.WLi + WOFF[L], Aiu[L], p.hsi, p.el_i, NITM, fin);
        else
            k_mma_gemm<128, 32><<<gbI, 256, SMEM128, SB>>>(p.Aih, p.Ail,
                p.WHi + WOFF[L], p.WLi + WOFF[L], Aiu[L], p.hsi, p.el_i, NITM, fin);
        int evBg = REC(SB);

        // ---- fused edges: item-dst on SA (el_u+hsu from SA, er from ci+Vui) ----
        if (L == 0) WAITE(SA, evCSR);
        if (F == 256) {
            k_edge256s<<<EDGE_BLOCKS, 256, 0, SA>>>(p.rp_i, p.srcs_i,
                (const float4*)p.el_u, (const float4*)(p.Vui + VOFF(L)), ci,
                p.hsu, outi, p.stats_i + L * 512, NITM, fin);
            k_edge256s<<<EDGE_BLOCKS, 256, 0, SB>>>(p.rp_u, p.srcs_u,
                (const float4*)p.el_i, (const float4*)(p.Viu + VOFF(L)), cu,
                p.hsi, outu, p.stats_u + L * 512, NUSR, fin);
        } else {
            k_edge128f<<<wgrid(NITM), 256, 0, SA>>>(p.rp_i, p.srcs_i,
                (const float4*)p.el_u, (const float4*)(p.Vui + VOFF(L)), ci,
                p.hsu, outi, NITM, fin);
            k_edge128f<<<wgrid(NUSR), 256, 0, SB>>>(p.rp_u, p.srcs_u,
                (const float4*)p.el_i, (const float4*)(p.Viu + VOFF(L)), cu,
                p.hsi, outu, NUSR, fin);
        }

        if (L < 3) {
            // BN apply item on SA (stats complete after edge_i on SA)
            WAITE(SA, evBg);   // writes Aih/Ail read by SB's gemm this layer
            k_bnapply<<<256, 256, 0, SA>>>(p.ni, p.hi, p.Aih, p.Ail, bn_i,
                                           p.stats_i + L * 512, L, NITM,
                                           (L == 2) ? 1 : 0);
            // BN apply user on SB
            WAITE(SB, evAg);   // writes Auh/Aul read by SA's gemm this layer
            k_bnapply<<<256, 256, 0, SB>>>(p.nu, p.hu, p.Auh, p.Aul, bn_u,
                                           p.stats_u + L * 512, L, NUSR,
                                           (L == 2) ? 1 : 0);
            // layer-boundary cross joins
            int evAe = REC(SA);
            int evBe = REC(SB);
            WAITE(SA, evBe);   // next SA gemm reads Auh/Aul (SB); edge_i reads hi (SA ok)
            WAITE(SB, evAe);   // next SB gemm reads Aih/Ail (SA); edge_u reads hu (SB ok)
            cu = p.hu;
            ci = p.hi;
            fin = FHID;
        } else {
            int evBf = REC(SB);
            WAITE(SA, evBf);
        }
    }
    (void)n_in; (void)out_size;
}

// round 10
// speedup vs baseline: 1.3187x; 1.0021x over previous
#include <cuda_runtime.h>
#include <cuda_bf16.h>
#include <math.h>
#include <stddef.h>
#include <stdint.h>

// ---------------- problem constants ----------------
#define NUSR 50000
#define NITM 20000
#define NEDG 400000
#define FIN0 128
#define FHID 256
#define NHEAD 4

// ---------------- device scratch (no allocs allowed) ----------------
__device__ float g_hu [(size_t)NUSR * FHID];
__device__ float g_hi [(size_t)NITM * FHID];
__device__ float g_hsu[(size_t)NUSR * FHID];
__device__ float g_hsi[(size_t)NITM * FHID];
__device__ float g_nu [(size_t)NUSR * FHID];
__device__ float g_ni [(size_t)NITM * FHID];
__device__ float g_el_u[NUSR * 4];
__device__ float g_el_i[NITM * 4];
__device__ int   g_rp_i[NITM + 1];
__device__ int   g_rp_u[NUSR + 1];
__device__ int   g_srcs_i[NEDG];
__device__ int   g_srcs_u[NEDG];
__device__ int   g_cur_i[NITM];
__device__ int   g_cur_u[NUSR];
__device__ float g_Vui[4 * FHID * NHEAD];
__device__ float g_Viu[4 * FHID * NHEAD];
__device__ float g_stats_i[3 * 512];
__device__ float g_stats_u[3 * 512];
__device__ int   g_part[64];
__device__ __nv_bfloat16 g_WHu[196608];
__device__ __nv_bfloat16 g_WLu[196608];
__device__ __nv_bfloat16 g_WHi[196608];
__device__ __nv_bfloat16 g_WLi[196608];
__device__ __nv_bfloat16 g_Auh[(size_t)NUSR * FHID];
__device__ __nv_bfloat16 g_Aul[(size_t)NUSR * FHID];
__device__ __nv_bfloat16 g_Aih[(size_t)NITM * FHID];
__device__ __nv_bfloat16 g_Ail[(size_t)NITM * FHID];

// ---------------- PTX helpers (baseline features only) ----------------
__device__ __forceinline__ uint32_t smem_u32(const void* p) {
    uint32_t a;
    asm("{ .reg .u64 t; cvta.to.shared.u64 t, %1; cvt.u32.u64 %0, t; }"
        : "=r"(a) : "l"(p));
    return a;
}
__device__ __forceinline__ void ldsm4(uint32_t* r, uint32_t addr) {
    asm volatile("ldmatrix.sync.aligned.m8n8.x4.shared.b16 {%0,%1,%2,%3}, [%4];"
        : "=r"(r[0]), "=r"(r[1]), "=r"(r[2]), "=r"(r[3]) : "r"(addr));
}
__device__ __forceinline__ void ldsm4t(uint32_t* r, uint32_t addr) {
    asm volatile("ldmatrix.sync.aligned.m8n8.x4.trans.shared.b16 {%0,%1,%2,%3}, [%4];"
        : "=r"(r[0]), "=r"(r[1]), "=r"(r[2]), "=r"(r[3]) : "r"(addr));
}
__device__ __forceinline__ void mma16816(float* c, const uint32_t* a,
                                         uint32_t b0, uint32_t b1) {
    asm volatile(
        "mma.sync.aligned.m16n8k16.row.col.f32.bf16.bf16.f32 "
        "{%0,%1,%2,%3}, {%4,%5,%6,%7}, {%8,%9}, {%0,%1,%2,%3};"
        : "+f"(c[0]), "+f"(c[1]), "+f"(c[2]), "+f"(c[3])
        : "r"(a[0]), "r"(a[1]), "r"(a[2]), "r"(a[3]), "r"(b0), "r"(b1));
}
#define CPA16(dst, src) \
    asm volatile("cp.async.cg.shared.global [%0], [%1], 16;" \
                 :: "r"(dst), "l"(src))
#define CP_COMMIT() asm volatile("cp.async.commit_group;")
#define CP_WAIT1()  asm volatile("cp.async.wait_group 1;" ::: "memory")
#define CP_WAIT0()  asm volatile("cp.async.wait_group 0;" ::: "memory")

// ---------------- tiny utility kernels ----------------
__global__ void k_noop() {}
__global__ void k_zeroi(int* p, int n) {
    int i = blockIdx.x * blockDim.x + threadIdx.x;
    if (i < n) p[i] = 0;
}
__global__ void k_zerof(float* p, int n) {
    int i = blockIdx.x * blockDim.x + threadIdx.x;
    if (i < n) p[i] = 0.f;
}
__global__ void k_copyi(const int* __restrict__ a, int* __restrict__ b, int n) {
    int i = blockIdx.x * blockDim.x + threadIdx.x;
    if (i < n) b[i] = a[i];
}

// ---------------- CSR construction ----------------
__global__ void k_count(const int* __restrict__ eu, const int* __restrict__ ei,
                        int* cu, int* ci) {
    int k = blockIdx.x * blockDim.x + threadIdx.x;
    if (k < NEDG) {
        atomicAdd(&ci[ei[k]], 1);
        atomicAdd(&cu[eu[k]], 1);
    }
}
__global__ void k_scan_blk(const int* __restrict__ cnt, int n,
                           int* __restrict__ rp, int* __restrict__ part) {
    __shared__ int ws[32];
    int tid = threadIdx.x;
    int i = blockIdx.x * 1024 + tid;
    int v = (i < n) ? cnt[i] : 0;
    int lane = tid & 31, w = tid >> 5;
    int x = v;
    #pragma unroll
    for (int o = 1; o < 32; o <<= 1) {
        int y = __shfl_up_sync(0xffffffffu, x, o);
        if (lane >= o) x += y;
    }
    if (lane == 31) ws[w] = x;
    __syncthreads();
    if (w == 0) {
        int t = ws[lane];
        #pragma unroll
        for (int o = 1; o < 32; o <<= 1) {
            int y = __shfl_up_sync(0xffffffffu, t, o);
            if (lane >= o) t += y;
        }
        ws[lane] = t;
    }
    __syncthreads();
    int incl = x + (w > 0 ? ws[w - 1] : 0);
    if (i < n) rp[i + 1] = incl;
    if (tid == 1023) part[blockIdx.x] = incl;
}
__global__ void k_scan_part(int* part, int nb) {
    __shared__ int w0sum;
    int tid = threadIdx.x;
    int v = (tid < nb) ? part[tid] : 0;
    int lane = tid & 31, w = tid >> 5;
    int x = v;
    #pragma unroll
    for (int o = 1; o < 32; o <<= 1) {
        int y = __shfl_up_sync(0xffffffffu, x, o);
        if (lane >= o) x += y;
    }
    if (w == 0 && lane == 31) w0sum = x;
    __syncthreads();
    int incl = x + (w ? w0sum : 0);
    if (tid < nb) part[tid] = incl - v;
}
__global__ void k_scan_add(int* __restrict__ rp, const int* __restrict__ part, int n) {
    int i = blockIdx.x * 1024 + threadIdx.x;
    if (i < n) rp[i + 1] += part[blockIdx.x];
    if (i == 0) rp[0] = 0;
}
__global__ void k_scatter(const int* __restrict__ eu, const int* __restrict__ ei,
                          int* cu, int* ci,
                          int* __restrict__ su, int* __restrict__ si) {
    int k = blockIdx.x * blockDim.x + threadIdx.x;
    if (k < NEDG) {
        int u = eu[k], it = ei[k];
        int p = atomicAdd(&ci[it], 1);
        si[p] = u;
        int q = atomicAdd(&cu[u], 1);
        su[q] = it;
    }
}

// ---------------- elementwise fp32 -> bf16 hi/lo split ----------------
__global__ void k_split(const float* __restrict__ X, __nv_bfloat16* __restrict__ xh,
                        __nv_bfloat16* __restrict__ xl, int total) {
    int id = blockIdx.x * blockDim.x + threadIdx.x;
    if (id >= total) return;
    float v = X[id];
    __nv_bfloat16 h = __float2bfloat16_rn(v);
    xh[id] = h;
    xl[id] = __float2bfloat16_rn(v - __bfloat162float(h));
}

// ---------------- batched collapseV: all layers, both sides, one launch -------
struct CVArgs { const float* W[8]; const float* A[8]; };  // [side*4 + L]
__global__ void k_collapseAll(CVArgs a, float* __restrict__ Vui,
                              float* __restrict__ Viu) {
    int t = blockIdx.x * blockDim.x + threadIdx.x;
    if (t >= 7168) return;
    int side = (t >= 3584) ? 1 : 0;
    int u = t - side * 3584;
    int L, off;
    if (u < 512)       { L = 0; off = 0; }
    else if (u < 1536) { L = 1; off = 512; }
    else if (u < 2560) { L = 2; off = 1536; }
    else               { L = 3; off = 2560; }
    int local = u - off;
    int k = local >> 2, h = local & 3;
    int F = (L == 3) ? 128 : 256;
    int dh = (L == 3) ? 32 : 64;
    const float* W = a.W[side * 4 + L];
    const float* A1 = a.A[side * 4 + L] + NHEAD * dh;
    float s = 0.f;
    for (int d = 0; d < dh; d++)
        s += W[(size_t)k * F + h * dh + d] * A1[h * dh + d];
    (side ? Viu : Vui)[L * FHID * NHEAD + local] = s;
}

// ---------------- tensor-core GEMM + fused el epilogue ----------------
template <int BN, int DH>
__global__ void __launch_bounds__((BN == 256) ? 512 : 256, 1)
k_mma_gemm(const __nv_bfloat16* __restrict__ Ah, const __nv_bfloat16* __restrict__ Al,
           const __nv_bfloat16* __restrict__ Bh, const __nv_bfloat16* __restrict__ Bl,
           const float* __restrict__ attA,
           float* __restrict__ C, float* __restrict__ el, int M, int K) {
    constexpr int NT = (BN == 256) ? 512 : 256;
    constexpr int SBSTR = BN * 2 + 16;
    constexpr int ASZ = 128 * 80;
    constexpr int BOFF = 2 * ASZ;
    constexpr int BSZ = 32 * SBSTR;
    constexpr int STAGE = BOFF + 2 * BSZ;
    constexpr int NBC = 32 * (BN / 8);

    extern __shared__ char smem[];
    uint32_t sb = smem_u32(smem);
    int tid = threadIdx.x;
    int wid = tid >> 5, lane = tid & 31;
    int wm = wid & 3, wn = wid >> 2;
    int bm = blockIdx.x * 128;

    float acc[2][8][4];
    #pragma unroll
    for (int i = 0; i < 2; i++)
        #pragma unroll
        for (int j = 0; j < 8; j++)
            #pragma unroll
            for (int q = 0; q < 4; q++) acc[i][j][q] = 0.f;

    int nch = K >> 5;

    auto load_stage = [&](int st, int kc) {
        uint32_t sbase = sb + st * STAGE;
        int k0 = kc << 5;
        #pragma unroll
        for (int c = tid; c < 512; c += NT) {
            int row = c >> 2, q = c & 3;
            int gr = bm + row;
            gr = gr < M ? gr : M - 1;
            size_t gi = (size_t)gr * K + k0 + q * 8;
            uint32_t d = sbase + row * 80 + q * 16;
            CPA16(d, Ah + gi);
            CPA16(d + ASZ, Al + gi);
        }
        #pragma unroll
        for (int c = tid; c < NBC; c += NT) {
            int k = c / (BN / 8), seg = c % (BN / 8);
            size_t gi = (size_t)(k0 + k) * BN + seg * 8;
            uint32_t d = sbase + BOFF + k * SBSTR + seg * 16;
            CPA16(d, Bh + gi);
            CPA16(d + BSZ, Bl + gi);
        }
        CP_COMMIT();
    };

    load_stage(0, 0);
    for (int kc = 0; kc < nch; kc++) {
        int cur = kc & 1;
        if (kc + 1 < nch) {
            load_stage(1 - cur, kc + 1);
            CP_WAIT1();
        } else {
            CP_WAIT0();
        }
        __syncthreads();
        uint32_t abase = sb + cur * STAGE;
        #pragma unroll
        for (int s = 0; s < 2; s++) {
            uint32_t Af[2][4], Alf[2][4];
            #pragma unroll
            for (int mt = 0; mt < 2; mt++) {
                uint32_t ad = abase +
                    (uint32_t)(wm * 32 + mt * 16 + (lane & 15)) * 80 +
                    s * 32 + (lane >> 4) * 16;
                ldsm4(Af[mt], ad);
                ldsm4(Alf[mt], ad + ASZ);
            }
            #pragma unroll
            for (int np = 0; np < 4; np++) {
                int g = lane >> 3, r = lane & 7;
                int kk = s * 16 + (g & 1) * 8 + r;
                int nn = wn * 64 + np * 16 + (g >> 1) * 8;
                uint32_t bd = abase + BOFF + (uint32_t)kk * SBSTR + nn * 2;
                uint32_t bh4[4], bl4[4];
                ldsm4t(bh4, bd);
                ldsm4t(bl4, bd + BSZ);
                #pragma unroll
                for (int mt = 0; mt < 2; mt++)
                    #pragma unroll
                    for (int sub = 0; sub < 2; sub++) {
                        float* a = acc[mt][np * 2 + sub];
                        mma16816(a, Af[mt], bh4[2 * sub], bh4[2 * sub + 1]);
                        mma16816(a, Af[mt], bl4[2 * sub], bl4[2 * sub + 1]);
                        mma16816(a, Alf[mt], bh4[2 * sub], bh4[2 * sub + 1]);
                    }
            }
        }
        __syncthreads();
    }

    constexpr int HPW = 64 / DH;
    int grp = lane >> 2, tq = lane & 3;
    #pragma unroll
    for (int mt = 0; mt < 2; mt++) {
        int r0 = bm + wm * 32 + mt * 16 + grp;
        int r1 = r0 + 8;
        #pragma unroll
        for (int nt = 0; nt < 8; nt++) {
            int col = wn * 64 + nt * 8 + tq * 2;
            if (r0 < M)
                *(float2*)(C + (size_t)r0 * BN + col) =
                    make_float2(acc[mt][nt][0], acc[mt][nt][1]);
            if (r1 < M)
                *(float2*)(C + (size_t)r1 * BN + col) =
                    make_float2(acc[mt][nt][2], acc[mt][nt][3]);
        }
        float s0[HPW], s1[HPW];
        #pragma unroll
        for (int p = 0; p < HPW; p++) { s0[p] = 0.f; s1[p] = 0.f; }
        #pragma unroll
        for (int nt = 0; nt < 8; nt++) {
            int part = (nt * 8) / DH;
            int col = wn * 64 + nt * 8 + tq * 2;
            float c0 = attA[col], c1 = attA[col + 1];
            s0[part] += c0 * acc[mt][nt][0] + c1 * acc[mt][nt][1];
            s1[part] += c0 * acc[mt][nt][2] + c1 * acc[mt][nt][3];
        }
        #pragma unroll
        for (int p = 0; p < HPW; p++) {
            s0[p] += __shfl_xor_sync(0xffffffffu, s0[p], 1);
            s0[p] += __shfl_xor_sync(0xffffffffu, s0[p], 2);
            s1[p] += __shfl_xor_sync(0xffffffffu, s1[p], 1);
            s1[p] += __shfl_xor_sync(0xffffffffu, s1[p], 2);
            if (tq == 0) {
                int h = wn * HPW + p;
                if (r0 < M) el[r0 * 4 + h] = s0[p];
                if (r1 < M) el[r1 * 4 + h] = s1[p];
            }
        }
    }
}

__device__ __forceinline__ float lrelu(float x, float s) { return x > 0.f ? x : s * x; }

// ---- fused edge kernel, F=256: er + 1-pass softmax-agg + BN stats ----
__global__ void __launch_bounds__(256)
k_edge256s(const int* __restrict__ rp, const int* __restrict__ srcs,
           const float4* __restrict__ el4, const float4* __restrict__ V4,
           const float* __restrict__ cdst, const float* __restrict__ hs,
           float* __restrict__ out, float* __restrict__ stats,
           int ndst, int fin) {
    __shared__ float s_st[512];
    int tid = threadIdx.x;
    for (int i = tid; i < 512; i += 256) s_st[i] = 0.f;
    __syncthreads();
    int lane = tid & 31, wloc = tid >> 5;
    bool loHalf = lane < 16;
    float sm0[4] = {0.f, 0.f, 0.f, 0.f}, sq0[4] = {0.f, 0.f, 0.f, 0.f};
    float sm1[4] = {0.f, 0.f, 0.f, 0.f}, sq1[4] = {0.f, 0.f, 0.f, 0.f};

    for (int w = blockIdx.x * 8 + wloc; w < ndst; w += gridDim.x * 8) {
        const float* c = cdst + (size_t)w * fin;
        float a0 = 0.f, a1 = 0.f, a2 = 0.f, a3 = 0.f;
        for (int k = lane; k < fin; k += 32) {
            float xv = c[k];
            float4 v = V4[k];
            a0 += xv * v.x; a1 += xv * v.y; a2 += xv * v.z; a3 += xv * v.w;
        }
        #pragma unroll
        for (int o = 16; o; o >>= 1) {
            a0 += __shfl_xor_sync(0xffffffffu, a0, o);
            a1 += __shfl_xor_sync(0xffffffffu, a1, o);
            a2 += __shfl_xor_sync(0xffffffffu, a2, o);
            a3 += __shfl_xor_sync(0xffffffffu, a3, o);
        }
        float erA = loHalf ? a0 : a1, erB = loHalf ? a2 : a3;

        int s0 = rp[w], s1 = rp[w + 1];
        float4 o0 = make_float4(0.f, 0.f, 0.f, 0.f);
        float4 o1 = make_float4(0.f, 0.f, 0.f, 0.f);
        if (s0 != s1) {
            float4 acc0 = make_float4(0.f, 0.f, 0.f, 0.f);
            float4 acc1 = make_float4(0.f, 0.f, 0.f, 0.f);
            float zA = 0.f, zB = 0.f;
            for (int j = s0; j < s1; j++) {
                int s = srcs[j];
                float4 e = el4[s];
                float eA = loHalf ? e.x : e.y, eB = loHalf ? e.z : e.w;
                float aA = expf(lrelu(eA + erA, 0.2f));
                float aB = expf(lrelu(eB + erB, 0.2f));
                const float4* row = (const float4*)(hs + (size_t)s * 256);
                float4 v0 = row[lane];
                float4 v1 = row[lane + 32];
                acc0.x += aA * v0.x; acc0.y += aA * v0.y;
                acc0.z += aA * v0.z; acc0.w += aA * v0.w;
                acc1.x += aB * v1.x; acc1.y += aB * v1.y;
                acc1.z += aB * v1.z; acc1.w += aB * v1.w;
                zA += aA; zB += aB;
            }
            float iA = 1.f / zA, iB = 1.f / zB;
            o0 = make_float4(acc0.x * iA, acc0.y * iA, acc0.z * iA, acc0.w * iA);
            o1 = make_float4(acc1.x * iB, acc1.y * iB, acc1.z * iB, acc1.w * iB);
        }
        float4* op = (float4*)(out + (size_t)w * 256);
        op[lane] = o0;
        op[lane + 32] = o1;
        sm0[0] += o0.x; sq0[0] += o0.x * o0.x;
        sm0[1] += o0.y; sq0[1] += o0.y * o0.y;
        sm0[2] += o0.z; sq0[2] += o0.z * o0.z;
        sm0[3] += o0.w; sq0[3] += o0.w * o0.w;
        sm1[0] += o1.x; sq1[0] += o1.x * o1.x;
        sm1[1] += o1.y; sq1[1] += o1.y * o1.y;
        sm1[2] += o1.z; sq1[2] += o1.z * o1.z;
        sm1[3] += o1.w; sq1[3] += o1.w * o1.w;
    }
    #pragma unroll
    for (int q = 0; q < 4; q++) {
        atomicAdd(&s_st[lane * 4 + q], sm0[q]);
        atomicAdd(&s_st[256 + lane * 4 + q], sq0[q]);
        atomicAdd(&s_st[128 + lane * 4 + q], sm1[q]);
        atomicAdd(&s_st[256 + 128 + lane * 4 + q], sq1[q]);
    }
    __syncthreads();
    for (int i = tid; i < 512; i += 256)
        atomicAdd(&stats[i], s_st[i]);
}

// ---- fused edge kernel, F=128 (dh=32): er + 1-pass softmax-agg ----
__global__ void k_edge128f(const int* __restrict__ rp, const int* __restrict__ srcs,
                           const float4* __restrict__ el4, const float4* __restrict__ V4,
                           const float* __restrict__ cdst, const float* __restrict__ hs,
                           float* __restrict__ out, int ndst, int fin) {
    int w = (blockIdx.x * blockDim.x + threadIdx.x) >> 5;
    int lane = threadIdx.x & 31;
    if (w >= ndst) return;
    const float* c = cdst + (size_t)w * fin;
    float a0 = 0.f, a1 = 0.f, a2 = 0.f, a3 = 0.f;
    for (int k = lane; k < fin; k += 32) {
        float xv = c[k];
        float4 v = V4[k];
        a0 += xv * v.x; a1 += xv * v.y; a2 += xv * v.z; a3 += xv * v.w;
    }
    #pragma unroll
    for (int o = 16; o; o >>= 1) {
        a0 += __shfl_xor_sync(0xffffffffu, a0, o);
        a1 += __shfl_xor_sync(0xffffffffu, a1, o);
        a2 += __shfl_xor_sync(0xffffffffu, a2, o);
        a3 += __shfl_xor_sync(0xffffffffu, a3, o);
    }
    int hsel = lane >> 3;
    float erS = (hsel == 0) ? a0 : (hsel == 1) ? a1 : (hsel == 2) ? a2 : a3;

    int s0 = rp[w], s1 = rp[w + 1];
    float4* o = (float4*)(out + (size_t)w * 128);
    if (s0 == s1) {
        o[lane] = make_float4(0.f, 0.f, 0.f, 0.f);
        return;
    }
    float4 acc = make_float4(0.f, 0.f, 0.f, 0.f);
    float z = 0.f;
    for (int j = s0; j < s1; j++) {
        int s = srcs[j];
        float4 e = el4[s];
        float eS = (hsel == 0) ? e.x : (hsel == 1) ? e.y : (hsel == 2) ? e.z : e.w;
        float a = expf(lrelu(eS + erS, 0.2f));
        const float4* row = (const float4*)(hs + (size_t)s * 128);
        float4 v = row[lane];
        acc.x += a * v.x; acc.y += a * v.y; acc.z += a * v.z; acc.w += a * v.w;
        z += a;
    }
    float iz = 1.f / z;
    o[lane] = make_float4(acc.x * iz, acc.y * iz, acc.z * iz, acc.w * iz);
}

// ---------------- BatchNorm apply (+act +bf16 split) ----------------
__global__ void k_bnapply(const float* __restrict__ x, float* __restrict__ y,
                          __nv_bfloat16* __restrict__ yh, __nv_bfloat16* __restrict__ yl,
                          const float* __restrict__ bn, const float* __restrict__ stats,
                          int L, int n, int use_tanh) {
    int c = threadIdx.x;
    float mu = stats[c] / (float)n;
    float var = stats[256 + c] / (float)n - mu * mu;
    float gamma = bn[(L * 2 + 0) * 256 + c];
    float beta  = bn[(L * 2 + 1) * 256 + c];
    float sc = gamma * rsqrtf(var + 1e-5f);
    float sh = beta - mu * sc;
    for (int r = blockIdx.x; r < n; r += gridDim.x) {
        size_t idx = (size_t)r * 256 + c;
        float v = sc * x[idx] + sh;
        v = use_tanh ? tanhf(v) : (v > 0.f ? v : 0.01f * v);
        y[idx] = v;
        __nv_bfloat16 h = __float2bfloat16_rn(v);
        yh[idx] = h;
        yl[idx] = __float2bfloat16_rn(v - __bfloat162float(h));
    }
}

// ---------------- static stream/event setup (pre-checkpoint) ----------------
namespace {
struct StreamInit {
    cudaStream_t s2 = 0;
    cudaEvent_t ev[32];
    bool ok = false;
    StreamInit() {
        if (cudaStreamCreateWithFlags(&s2, cudaStreamNonBlocking) != cudaSuccess) return;
        for (int i = 0; i < 32; i++)
            if (cudaEventCreateWithFlags(&ev[i], cudaEventDisableTiming) != cudaSuccess)
                return;
        k_noop<<<1, 32>>>();
        k_noop<<<1, 32, 0, s2>>>();
        for (int i = 0; i < 32; i++) cudaEventRecord(ev[i], (i & 1) ? s2 : 0);
        if (cudaDeviceSynchronize() != cudaSuccess) return;
        if (cudaGetLastError() != cudaSuccess) return;
        ok = true;
    }
};
StreamInit g_si;
}

// ---------------- host orchestration ----------------
static inline int wgrid(int nwarp) { return (nwarp * 32 + 255) / 256; }

struct Ptrs {
    float *hu, *hi, *hsu, *hsi, *nu, *ni;
    float *el_u, *el_i, *Vui, *Viu, *stats_i, *stats_u;
    __nv_bfloat16 *WHu, *WLu, *WHi, *WLi, *Auh, *Aul, *Aih, *Ail;
    int *rp_i, *rp_u, *srcs_i, *srcs_u, *cur_i, *cur_u, *part;
};

static void get_ptrs(Ptrs& p) {
    cudaGetSymbolAddress((void**)&p.hu, g_hu);
    cudaGetSymbolAddress((void**)&p.hi, g_hi);
    cudaGetSymbolAddress((void**)&p.hsu, g_hsu);
    cudaGetSymbolAddress((void**)&p.hsi, g_hsi);
    cudaGetSymbolAddress((void**)&p.nu, g_nu);
    cudaGetSymbolAddress((void**)&p.ni, g_ni);
    cudaGetSymbolAddress((void**)&p.el_u, g_el_u);
    cudaGetSymbolAddress((void**)&p.el_i, g_el_i);
    cudaGetSymbolAddress((void**)&p.Vui, g_Vui);
    cudaGetSymbolAddress((void**)&p.Viu, g_Viu);
    cudaGetSymbolAddress((void**)&p.stats_i, g_stats_i);
    cudaGetSymbolAddress((void**)&p.stats_u, g_stats_u);
    cudaGetSymbolAddress((void**)&p.WHu, g_WHu);
    cudaGetSymbolAddress((void**)&p.WLu, g_WLu);
    cudaGetSymbolAddress((void**)&p.WHi, g_WHi);
    cudaGetSymbolAddress((void**)&p.WLi, g_WLi);
    cudaGetSymbolAddress((void**)&p.Auh, g_Auh);
    cudaGetSymbolAddress((void**)&p.Aul, g_Aul);
    cudaGetSymbolAddress((void**)&p.Aih, g_Aih);
    cudaGetSymbolAddress((void**)&p.Ail, g_Ail);
    cudaGetSymbolAddress((void**)&p.rp_i, g_rp_i);
    cudaGetSymbolAddress((void**)&p.rp_u, g_rp_u);
    cudaGetSymbolAddress((void**)&p.srcs_i, g_srcs_i);
    cudaGetSymbolAddress((void**)&p.srcs_u, g_srcs_u);
    cudaGetSymbolAddress((void**)&p.cur_i, g_cur_i);
    cudaGetSymbolAddress((void**)&p.cur_u, g_cur_u);
    cudaGetSymbolAddress((void**)&p.part, g_part);
}

#define SMEM256 (2 * (2 * 128 * 80 + 2 * 32 * (256 * 2 + 16)))
#define SMEM128 (2 * (2 * 128 * 80 + 2 * 32 * (128 * 2 + 16)))
#define EDGE_BLOCKS 592

static const int WOFF[4] = {0, 32768, 98304, 163840};
static const int WSZ[4]  = {32768, 65536, 65536, 32768};
#define VOFF(L) ((L) * FHID * NHEAD)

static void scan(const int* cnt, int n, int* rp, int* part, cudaStream_t st) {
    int nb = (n + 1023) / 1024;
    k_scan_blk<<<nb, 1024, 0, st>>>(cnt, n, rp, part);
    k_scan_part<<<1, 64, 0, st>>>(part, nb);
    k_scan_add<<<nb, 1024, 0, st>>>(rp, part, n);
}

extern "C" void kernel_launch(void* const* d_in, const int* in_sizes, int n_in,
                              void* d_out, int out_size) {
    Ptrs p;
    get_ptrs(p);
    cudaFuncSetAttribute(k_mma_gemm<256, 64>,
                         cudaFuncAttributeMaxDynamicSharedMemorySize, SMEM256);
    cudaFuncSetAttribute(k_mma_gemm<128, 32>,
                         cudaFuncAttributeMaxDynamicSharedMemorySize, SMEM128);

    const float* x_user = (const float*)d_in[0];
    const float* x_item = (const float*)d_in[1];
    const int*   eu     = (const int*)d_in[2];
    const int*   ei     = (const int*)d_in[3];

    bool dictOrder = (in_sizes[5] < 10000);
    const float *Wui[4], *Aui[4], *Wiu[4], *Aiu[4];
    for (int L = 0; L < 4; L++) {
        if (dictOrder) {
            Wui[L] = (const float*)d_in[4 + L * 4 + 0];
            Aui[L] = (const float*)d_in[4 + L * 4 + 1];
            Wiu[L] = (const float*)d_in[4 + L * 4 + 2];
            Aiu[L] = (const float*)d_in[4 + L * 4 + 3];
        } else {
            Wui[L] = (const float*)d_in[4 + L * 4 + 0];
            Wiu[L] = (const float*)d_in[4 + L * 4 + 1];
            Aui[L] = (const float*)d_in[4 + L * 4 + 2];
            Aiu[L] = (const float*)d_in[4 + L * 4 + 3];
        }
    }
    const float* bn_u = (const float*)d_in[20];
    const float* bn_i = (const float*)d_in[21];
    float* out = (float*)d_out;

    cudaStream_t SA = 0;
    cudaStream_t SB = g_si.ok ? g_si.s2 : (cudaStream_t)0;
    bool fork = g_si.ok;
    int ec = 0;
    auto REC = [&](cudaStream_t st) -> int {
        if (!fork) return -1;
        int i = ec++;
        cudaEventRecord(g_si.ev[i], st);
        return i;
    };
    auto WAITE = [&](cudaStream_t st, int i) {
        if (fork && i >= 0) cudaStreamWaitEvent(st, g_si.ev[i], 0);
    };

    // ---- capture-legal fork ----
    int evFork = REC(SA);
    WAITE(SB, evFork);

    // ---- SA prologue: critical path to user GEMM L0 ----
    k_zerof<<<6, 256, 0, SA>>>(p.stats_i, 3 * 512);
    k_split<<<(NUSR * FIN0 + 255) / 256, 256, 0, SA>>>(x_user, p.Auh, p.Aul, NUSR * FIN0);
    k_split<<<(WSZ[0] + 255) / 256, 256, 0, SA>>>(Wui[0], p.WHu + WOFF[0],
                                                  p.WLu + WOFF[0], WSZ[0]);

    // ---- SB prologue: item split, CSR, batched collapseV, W0 item ----
    k_split<<<(NITM * FIN0 + 255) / 256, 256, 0, SB>>>(x_item, p.Aih, p.Ail, NITM * FIN0);
    k_zeroi<<<(NUSR + 255) / 256, 256, 0, SB>>>(p.cur_u, NUSR);
    k_zeroi<<<(NITM + 255) / 256, 256, 0, SB>>>(p.cur_i, NITM);
    k_count<<<(NEDG + 255) / 256, 256, 0, SB>>>(eu, ei, p.cur_u, p.cur_i);
    scan(p.cur_i, NITM, p.rp_i, p.part, SB);
    scan(p.cur_u, NUSR, p.rp_u, p.part, SB);
    k_copyi<<<(NITM + 255) / 256, 256, 0, SB>>>(p.rp_i, p.cur_i, NITM);
    k_copyi<<<(NUSR + 255) / 256, 256, 0, SB>>>(p.rp_u, p.cur_u, NUSR);
    k_scatter<<<(NEDG + 255) / 256, 256, 0, SB>>>(eu, ei, p.cur_u, p.cur_i,
                                                  p.srcs_u, p.srcs_i);
    {
        CVArgs cva;
        for (int L = 0; L < 4; L++) {
            cva.W[L] = Wui[L];  cva.A[L] = Aui[L];
            cva.W[4 + L] = Wiu[L];  cva.A[4 + L] = Aiu[L];
        }
        k_collapseAll<<<28, 256, 0, SB>>>(cva, p.Vui, p.Viu);
    }
    int evPre = REC(SB);   // covers CSR + all V (stream-ordered)
    k_zerof<<<6, 256, 0, SB>>>(p.stats_u, 3 * 512);
    k_split<<<(WSZ[0] + 255) / 256, 256, 0, SB>>>(Wiu[0], p.WHi + WOFF[0],
                                                  p.WLi + WOFF[0], WSZ[0]);

    const float* cu = x_user;
    const float* ci = x_item;
    int fin = FIN0;
    for (int L = 0; L < 4; L++) {
        int F = (L == 3) ? 128 : 256;
        float* outi = (L == 3) ? (out + (size_t)NUSR * 128) : p.ni;
        float* outu = (L == 3) ? out : p.nu;
        int gbU = (NUSR + 127) / 128, gbI = (NITM + 127) / 128;

        // ---- SA: user GEMM (+el_u) ----
        if (F == 256)
            k_mma_gemm<256, 64><<<gbU, 512, SMEM256, SA>>>(p.Auh, p.Aul,
                p.WHu + WOFF[L], p.WLu + WOFF[L], Aui[L], p.hsu, p.el_u, NUSR, fin);
        else
            k_mma_gemm<128, 32><<<gbU, 256, SMEM128, SA>>>(p.Auh, p.Aul,
                p.WHu + WOFF[L], p.WLu + WOFF[L], Aui[L], p.hsu, p.el_u, NUSR, fin);
        int evAg = REC(SA);

        // ---- SB: item GEMM (+el_i) ----
        if (F == 256)
            k_mma_gemm<256, 64><<<gbI, 512, SMEM256, SB>>>(p.Aih, p.Ail,
                p.WHi + WOFF[L], p.WLi + WOFF[L], Aiu[L], p.hsi, p.el_i, NITM, fin);
        else
            k_mma_gemm<128, 32><<<gbI, 256, SMEM128, SB>>>(p.Aih, p.Ail,
                p.WHi + WOFF[L], p.WLi + WOFF[L], Aiu[L], p.hsi, p.el_i, NITM, fin);
        int evBg = REC(SB);

        // ---- deferred weight splits for L1..3 (off the L0 critical path) ----
        if (L == 0) {
            for (int l = 1; l < 4; l++) {
                k_split<<<(WSZ[l] + 255) / 256, 256, 0, SA>>>(Wui[l],
                    p.WHu + WOFF[l], p.WLu + WOFF[l], WSZ[l]);
                k_split<<<(WSZ[l] + 255) / 256, 256, 0, SB>>>(Wiu[l],
                    p.WHi + WOFF[l], p.WLi + WOFF[l], WSZ[l]);
            }
        }

        // ---- fused edges ----
        if (L == 0) WAITE(SA, evPre);   // CSR + Vui from SB
        if (F == 256) {
            k_edge256s<<<EDGE_BLOCKS, 256, 0, SA>>>(p.rp_i, p.srcs_i,
                (const float4*)p.el_u, (const float4*)(p.Vui + VOFF(L)), ci,
                p.hsu, outi, p.stats_i + L * 512, NITM, fin);
            k_edge256s<<<EDGE_BLOCKS, 256, 0, SB>>>(p.rp_u, p.srcs_u,
                (const float4*)p.el_i, (const float4*)(p.Viu + VOFF(L)), cu,
                p.hsi, outu, p.stats_u + L * 512, NUSR, fin);
        } else {
            k_edge128f<<<wgrid(NITM), 256, 0, SA>>>(p.rp_i, p.srcs_i,
                (const float4*)p.el_u, (const float4*)(p.Vui + VOFF(L)), ci,
                p.hsu, outi, NITM, fin);
            k_edge128f<<<wgrid(NUSR), 256, 0, SB>>>(p.rp_u, p.srcs_u,
                (const float4*)p.el_i, (const float4*)(p.Viu + VOFF(L)), cu,
                p.hsi, outu, NUSR, fin);
        }

        if (L < 3) {
            WAITE(SA, evBg);
            k_bnapply<<<256, 256, 0, SA>>>(p.ni, p.hi, p.Aih, p.Ail, bn_i,
                                           p.stats_i + L * 512, L, NITM,
                                           (L == 2) ? 1 : 0);
            WAITE(SB, evAg);
            k_bnapply<<<256, 256, 0, SB>>>(p.nu, p.hu, p.Auh, p.Aul, bn_u,
                                           p.stats_u + L * 512, L, NUSR,
                                           (L == 2) ? 1 : 0);
            int evAe = REC(SA);
            int evBe = REC(SB);
            WAITE(SA, evBe);
            WAITE(SB, evAe);
            cu = p.hu;
            ci = p.hi;
            fin = FHID;
        } else {
            int evBf = REC(SB);
            WAITE(SA, evBf);
        }
    }
    (void)n_in; (void)out_size;
}

// round 11
// speedup vs baseline: 1.5706x; 1.1910x over previous
#include <cuda_runtime.h>
#include <cuda_bf16.h>
#include <math.h>
#include <stddef.h>
#include <stdint.h>

// ---------------- problem constants ----------------
#define NUSR 50000
#define NITM 20000
#define NEDG 400000
#define FIN0 128
#define FHID 256
#define NHEAD 4

// ---------------- device scratch (no allocs allowed) ----------------
__device__ float g_hu [(size_t)NUSR * FHID];
__device__ float g_hi [(size_t)NITM * FHID];
__device__ float g_hsu[(size_t)NUSR * FHID];
__device__ float g_hsi[(size_t)NITM * FHID];
__device__ float g_nu [(size_t)NUSR * FHID];
__device__ float g_ni [(size_t)NITM * FHID];
__device__ float g_el_u[NUSR * 4];
__device__ float g_el_i[NITM * 4];
__device__ int   g_rp_i[NITM + 1];
__device__ int   g_rp_u[NUSR + 1];
__device__ int   g_srcs_i[NEDG];
__device__ int   g_srcs_u[NEDG];
__device__ int   g_cur_i[NITM];
__device__ int   g_cur_u[NUSR];
__device__ float g_Vui[4 * FHID * NHEAD];
__device__ float g_Viu[4 * FHID * NHEAD];
__device__ float g_stats_i[3 * 512];
__device__ float g_stats_u[3 * 512];
__device__ int   g_part[64];
__device__ __nv_bfloat16 g_WHu[196608];
__device__ __nv_bfloat16 g_WLu[196608];
__device__ __nv_bfloat16 g_WHi[196608];
__device__ __nv_bfloat16 g_WLi[196608];
__device__ __nv_bfloat16 g_Auh[(size_t)NUSR * FHID];
__device__ __nv_bfloat16 g_Aul[(size_t)NUSR * FHID];
__device__ __nv_bfloat16 g_Aih[(size_t)NITM * FHID];
__device__ __nv_bfloat16 g_Ail[(size_t)NITM * FHID];

// ---------------- PTX helpers (baseline features only) ----------------
__device__ __forceinline__ uint32_t smem_u32(const void* p) {
    uint32_t a;
    asm("{ .reg .u64 t; cvta.to.shared.u64 t, %1; cvt.u32.u64 %0, t; }"
        : "=r"(a) : "l"(p));
    return a;
}
__device__ __forceinline__ void ldsm4(uint32_t* r, uint32_t addr) {
    asm volatile("ldmatrix.sync.aligned.m8n8.x4.shared.b16 {%0,%1,%2,%3}, [%4];"
        : "=r"(r[0]), "=r"(r[1]), "=r"(r[2]), "=r"(r[3]) : "r"(addr));
}
__device__ __forceinline__ void ldsm4t(uint32_t* r, uint32_t addr) {
    asm volatile("ldmatrix.sync.aligned.m8n8.x4.trans.shared.b16 {%0,%1,%2,%3}, [%4];"
        : "=r"(r[0]), "=r"(r[1]), "=r"(r[2]), "=r"(r[3]) : "r"(addr));
}
__device__ __forceinline__ void mma16816(float* c, const uint32_t* a,
                                         uint32_t b0, uint32_t b1) {
    asm volatile(
        "mma.sync.aligned.m16n8k16.row.col.f32.bf16.bf16.f32 "
        "{%0,%1,%2,%3}, {%4,%5,%6,%7}, {%8,%9}, {%0,%1,%2,%3};"
        : "+f"(c[0]), "+f"(c[1]), "+f"(c[2]), "+f"(c[3])
        : "r"(a[0]), "r"(a[1]), "r"(a[2]), "r"(a[3]), "r"(b0), "r"(b1));
}
#define CPA16(dst, src) \
    asm volatile("cp.async.cg.shared.global [%0], [%1], 16;" \
                 :: "r"(dst), "l"(src))
#define CP_COMMIT() asm volatile("cp.async.commit_group;")
#define CP_WAIT1()  asm volatile("cp.async.wait_group 1;" ::: "memory")
#define CP_WAIT0()  asm volatile("cp.async.wait_group 0;" ::: "memory")

__device__ __forceinline__ uint32_t pack_bf16x2(float a, float b) {
    return ((uint32_t)__bfloat16_as_ushort(__float2bfloat16_rn(b)) << 16) |
           __bfloat16_as_ushort(__float2bfloat16_rn(a));
}
__device__ __forceinline__ float fast_tanh(float x) {
    x = fminf(fmaxf(x, -15.f), 15.f);
    float e = __expf(2.f * x);
    return (e - 1.f) / (e + 1.f);
}

// ---------------- tiny utility kernels ----------------
__global__ void k_noop() {}
__global__ void k_zeroi(int* p, int n) {
    int i = blockIdx.x * blockDim.x + threadIdx.x;
    if (i < n) p[i] = 0;
}
__global__ void k_zerof(float* p, int n) {
    int i = blockIdx.x * blockDim.x + threadIdx.x;
    if (i < n) p[i] = 0.f;
}
__global__ void k_copyi(const int* __restrict__ a, int* __restrict__ b, int n) {
    int i = blockIdx.x * blockDim.x + threadIdx.x;
    if (i < n) b[i] = a[i];
}

// ---------------- CSR construction ----------------
__global__ void k_count(const int* __restrict__ eu, const int* __restrict__ ei,
                        int* cu, int* ci) {
    int k = blockIdx.x * blockDim.x + threadIdx.x;
    if (k < NEDG) {
        atomicAdd(&ci[ei[k]], 1);
        atomicAdd(&cu[eu[k]], 1);
    }
}
__global__ void k_scan_blk(const int* __restrict__ cnt, int n,
                           int* __restrict__ rp, int* __restrict__ part) {
    __shared__ int ws[32];
    int tid = threadIdx.x;
    int i = blockIdx.x * 1024 + tid;
    int v = (i < n) ? cnt[i] : 0;
    int lane = tid & 31, w = tid >> 5;
    int x = v;
    #pragma unroll
    for (int o = 1; o < 32; o <<= 1) {
        int y = __shfl_up_sync(0xffffffffu, x, o);
        if (lane >= o) x += y;
    }
    if (lane == 31) ws[w] = x;
    __syncthreads();
    if (w == 0) {
        int t = ws[lane];
        #pragma unroll
        for (int o = 1; o < 32; o <<= 1) {
            int y = __shfl_up_sync(0xffffffffu, t, o);
            if (lane >= o) t += y;
        }
        ws[lane] = t;
    }
    __syncthreads();
    int incl = x + (w > 0 ? ws[w - 1] : 0);
    if (i < n) rp[i + 1] = incl;
    if (tid == 1023) part[blockIdx.x] = incl;
}
__global__ void k_scan_part(int* part, int nb) {
    __shared__ int w0sum;
    int tid = threadIdx.x;
    int v = (tid < nb) ? part[tid] : 0;
    int lane = tid & 31, w = tid >> 5;
    int x = v;
    #pragma unroll
    for (int o = 1; o < 32; o <<= 1) {
        int y = __shfl_up_sync(0xffffffffu, x, o);
        if (lane >= o) x += y;
    }
    if (w == 0 && lane == 31) w0sum = x;
    __syncthreads();
    int incl = x + (w ? w0sum : 0);
    if (tid < nb) part[tid] = incl - v;
}
__global__ void k_scan_add(int* __restrict__ rp, const int* __restrict__ part, int n) {
    int i = blockIdx.x * 1024 + threadIdx.x;
    if (i < n) rp[i + 1] += part[blockIdx.x];
    if (i == 0) rp[0] = 0;
}
__global__ void k_scatter(const int* __restrict__ eu, const int* __restrict__ ei,
                          int* cu, int* ci,
                          int* __restrict__ su, int* __restrict__ si) {
    int k = blockIdx.x * blockDim.x + threadIdx.x;
    if (k < NEDG) {
        int u = eu[k], it = ei[k];
        int p = atomicAdd(&ci[it], 1);
        si[p] = u;
        int q = atomicAdd(&cu[u], 1);
        su[q] = it;
    }
}

// ------- vectorized fp32 -> bf16 hi/lo split: 4 elems per thread -------
__global__ void k_split4(const float4* __restrict__ X, uint2* __restrict__ xh,
                         uint2* __restrict__ xl, int total4) {
    int id = blockIdx.x * blockDim.x + threadIdx.x;
    if (id >= total4) return;
    float4 v = X[id];
    float hx = __bfloat162float(__float2bfloat16_rn(v.x));
    float hy = __bfloat162float(__float2bfloat16_rn(v.y));
    float hz = __bfloat162float(__float2bfloat16_rn(v.z));
    float hw = __bfloat162float(__float2bfloat16_rn(v.w));
    xh[id] = make_uint2(pack_bf16x2(v.x, v.y), pack_bf16x2(v.z, v.w));
    xl[id] = make_uint2(pack_bf16x2(v.x - hx, v.y - hy),
                        pack_bf16x2(v.z - hz, v.w - hw));
}

// ---------------- batched collapseV ----------------
struct CVArgs { const float* W[8]; const float* A[8]; };
__global__ void k_collapseAll(CVArgs a, float* __restrict__ Vui,
                              float* __restrict__ Viu) {
    int t = blockIdx.x * blockDim.x + threadIdx.x;
    if (t >= 7168) return;
    int side = (t >= 3584) ? 1 : 0;
    int u = t - side * 3584;
    int L, off;
    if (u < 512)       { L = 0; off = 0; }
    else if (u < 1536) { L = 1; off = 512; }
    else if (u < 2560) { L = 2; off = 1536; }
    else               { L = 3; off = 2560; }
    int local = u - off;
    int k = local >> 2, h = local & 3;
    int F = (L == 3) ? 128 : 256;
    int dh = (L == 3) ? 32 : 64;
    const float* W = a.W[side * 4 + L];
    const float* A1 = a.A[side * 4 + L] + NHEAD * dh;
    float s = 0.f;
    for (int d = 0; d < dh; d++)
        s += W[(size_t)k * F + h * dh + d] * A1[h * dh + d];
    (side ? Viu : Vui)[L * FHID * NHEAD + local] = s;
}

// ---------------- tensor-core GEMM + fused el epilogue ----------------
template <int BN, int DH>
__global__ void __launch_bounds__((BN == 256) ? 512 : 256, 1)
k_mma_gemm(const __nv_bfloat16* __restrict__ Ah, const __nv_bfloat16* __restrict__ Al,
           const __nv_bfloat16* __restrict__ Bh, const __nv_bfloat16* __restrict__ Bl,
           const float* __restrict__ attA,
           float* __restrict__ C, float* __restrict__ el, int M, int K) {
    constexpr int NT = (BN == 256) ? 512 : 256;
    constexpr int SBSTR = BN * 2 + 16;
    constexpr int ASZ = 128 * 80;
    constexpr int BOFF = 2 * ASZ;
    constexpr int BSZ = 32 * SBSTR;
    constexpr int STAGE = BOFF + 2 * BSZ;
    constexpr int NBC = 32 * (BN / 8);

    extern __shared__ char smem[];
    uint32_t sb = smem_u32(smem);
    int tid = threadIdx.x;
    int wid = tid >> 5, lane = tid & 31;
    int wm = wid & 3, wn = wid >> 2;
    int bm = blockIdx.x * 128;

    float acc[2][8][4];
    #pragma unroll
    for (int i = 0; i < 2; i++)
        #pragma unroll
        for (int j = 0; j < 8; j++)
            #pragma unroll
            for (int q = 0; q < 4; q++) acc[i][j][q] = 0.f;

    int nch = K >> 5;

    auto load_stage = [&](int st, int kc) {
        uint32_t sbase = sb + st * STAGE;
        int k0 = kc << 5;
        #pragma unroll
        for (int c = tid; c < 512; c += NT) {
            int row = c >> 2, q = c & 3;
            int gr = bm + row;
            gr = gr < M ? gr : M - 1;
            size_t gi = (size_t)gr * K + k0 + q * 8;
            uint32_t d = sbase + row * 80 + q * 16;
            CPA16(d, Ah + gi);
            CPA16(d + ASZ, Al + gi);
        }
        #pragma unroll
        for (int c = tid; c < NBC; c += NT) {
            int k = c / (BN / 8), seg = c % (BN / 8);
            size_t gi = (size_t)(k0 + k) * BN + seg * 8;
            uint32_t d = sbase + BOFF + k * SBSTR + seg * 16;
            CPA16(d, Bh + gi);
            CPA16(d + BSZ, Bl + gi);
        }
        CP_COMMIT();
    };

    load_stage(0, 0);
    for (int kc = 0; kc < nch; kc++) {
        int cur = kc & 1;
        if (kc + 1 < nch) {
            load_stage(1 - cur, kc + 1);
            CP_WAIT1();
        } else {
            CP_WAIT0();
        }
        __syncthreads();
        uint32_t abase = sb + cur * STAGE;
        #pragma unroll
        for (int s = 0; s < 2; s++) {
            uint32_t Af[2][4], Alf[2][4];
            #pragma unroll
            for (int mt = 0; mt < 2; mt++) {
                uint32_t ad = abase +
                    (uint32_t)(wm * 32 + mt * 16 + (lane & 15)) * 80 +
                    s * 32 + (lane >> 4) * 16;
                ldsm4(Af[mt], ad);
                ldsm4(Alf[mt], ad + ASZ);
            }
            #pragma unroll
            for (int np = 0; np < 4; np++) {
                int g = lane >> 3, r = lane & 7;
                int kk = s * 16 + (g & 1) * 8 + r;
                int nn = wn * 64 + np * 16 + (g >> 1) * 8;
                uint32_t bd = abase + BOFF + (uint32_t)kk * SBSTR + nn * 2;
                uint32_t bh4[4], bl4[4];
                ldsm4t(bh4, bd);
                ldsm4t(bl4, bd + BSZ);
                #pragma unroll
                for (int mt = 0; mt < 2; mt++)
                    #pragma unroll
                    for (int sub = 0; sub < 2; sub++) {
                        float* a = acc[mt][np * 2 + sub];
                        mma16816(a, Af[mt], bh4[2 * sub], bh4[2 * sub + 1]);
                        mma16816(a, Af[mt], bl4[2 * sub], bl4[2 * sub + 1]);
                        mma16816(a, Alf[mt], bh4[2 * sub], bh4[2 * sub + 1]);
                    }
            }
        }
        __syncthreads();
    }

    constexpr int HPW = 64 / DH;
    int grp = lane >> 2, tq = lane & 3;
    #pragma unroll
    for (int mt = 0; mt < 2; mt++) {
        int r0 = bm + wm * 32 + mt * 16 + grp;
        int r1 = r0 + 8;
        #pragma unroll
        for (int nt = 0; nt < 8; nt++) {
            int col = wn * 64 + nt * 8 + tq * 2;
            if (r0 < M)
                *(float2*)(C + (size_t)r0 * BN + col) =
                    make_float2(acc[mt][nt][0], acc[mt][nt][1]);
            if (r1 < M)
                *(float2*)(C + (size_t)r1 * BN + col) =
                    make_float2(acc[mt][nt][2], acc[mt][nt][3]);
        }
        float s0[HPW], s1[HPW];
        #pragma unroll
        for (int p = 0; p < HPW; p++) { s0[p] = 0.f; s1[p] = 0.f; }
        #pragma unroll
        for (int nt = 0; nt < 8; nt++) {
            int part = (nt * 8) / DH;
            int col = wn * 64 + nt * 8 + tq * 2;
            float c0 = attA[col], c1 = attA[col + 1];
            s0[part] += c0 * acc[mt][nt][0] + c1 * acc[mt][nt][1];
            s1[part] += c0 * acc[mt][nt][2] + c1 * acc[mt][nt][3];
        }
        #pragma unroll
        for (int p = 0; p < HPW; p++) {
            s0[p] += __shfl_xor_sync(0xffffffffu, s0[p], 1);
            s0[p] += __shfl_xor_sync(0xffffffffu, s0[p], 2);
            s1[p] += __shfl_xor_sync(0xffffffffu, s1[p], 1);
            s1[p] += __shfl_xor_sync(0xffffffffu, s1[p], 2);
            if (tq == 0) {
                int h = wn * HPW + p;
                if (r0 < M) el[r0 * 4 + h] = s0[p];
                if (r1 < M) el[r1 * 4 + h] = s1[p];
            }
        }
    }
}

__device__ __forceinline__ float lrelu(float x, float s) { return x > 0.f ? x : s * x; }

// ---- fused edge kernel, F=256: er + 1-pass softmax-agg + BN stats ----
__global__ void __launch_bounds__(256)
k_edge256s(const int* __restrict__ rp, const int* __restrict__ srcs,
           const float4* __restrict__ el4, const float4* __restrict__ V4,
           const float* __restrict__ cdst, const float* __restrict__ hs,
           float* __restrict__ out, float* __restrict__ stats,
           int ndst, int fin) {
    __shared__ float s_st[512];
    int tid = threadIdx.x;
    for (int i = tid; i < 512; i += 256) s_st[i] = 0.f;
    __syncthreads();
    int lane = tid & 31, wloc = tid >> 5;
    bool loHalf = lane < 16;
    float sm0[4] = {0.f, 0.f, 0.f, 0.f}, sq0[4] = {0.f, 0.f, 0.f, 0.f};
    float sm1[4] = {0.f, 0.f, 0.f, 0.f}, sq1[4] = {0.f, 0.f, 0.f, 0.f};

    for (int w = blockIdx.x * 8 + wloc; w < ndst; w += gridDim.x * 8) {
        const float* c = cdst + (size_t)w * fin;
        float a0 = 0.f, a1 = 0.f, a2 = 0.f, a3 = 0.f;
        for (int k = lane; k < fin; k += 32) {
            float xv = c[k];
            float4 v = V4[k];
            a0 += xv * v.x; a1 += xv * v.y; a2 += xv * v.z; a3 += xv * v.w;
        }
        #pragma unroll
        for (int o = 16; o; o >>= 1) {
            a0 += __shfl_xor_sync(0xffffffffu, a0, o);
            a1 += __shfl_xor_sync(0xffffffffu, a1, o);
            a2 += __shfl_xor_sync(0xffffffffu, a2, o);
            a3 += __shfl_xor_sync(0xffffffffu, a3, o);
        }
        float erA = loHalf ? a0 : a1, erB = loHalf ? a2 : a3;

        int s0 = rp[w], s1 = rp[w + 1];
        float4 o0 = make_float4(0.f, 0.f, 0.f, 0.f);
        float4 o1 = make_float4(0.f, 0.f, 0.f, 0.f);
        if (s0 != s1) {
            float4 acc0 = make_float4(0.f, 0.f, 0.f, 0.f);
            float4 acc1 = make_float4(0.f, 0.f, 0.f, 0.f);
            float zA = 0.f, zB = 0.f;
            for (int j = s0; j < s1; j++) {
                int s = srcs[j];
                float4 e = el4[s];
                float eA = loHalf ? e.x : e.y, eB = loHalf ? e.z : e.w;
                float aA = __expf(lrelu(eA + erA, 0.2f));
                float aB = __expf(lrelu(eB + erB, 0.2f));
                const float4* row = (const float4*)(hs + (size_t)s * 256);
                float4 v0 = row[lane];
                float4 v1 = row[lane + 32];
                acc0.x += aA * v0.x; acc0.y += aA * v0.y;
                acc0.z += aA * v0.z; acc0.w += aA * v0.w;
                acc1.x += aB * v1.x; acc1.y += aB * v1.y;
                acc1.z += aB * v1.z; acc1.w += aB * v1.w;
                zA += aA; zB += aB;
            }
            float iA = 1.f / zA, iB = 1.f / zB;
            o0 = make_float4(acc0.x * iA, acc0.y * iA, acc0.z * iA, acc0.w * iA);
            o1 = make_float4(acc1.x * iB, acc1.y * iB, acc1.z * iB, acc1.w * iB);
        }
        float4* op = (float4*)(out + (size_t)w * 256);
        op[lane] = o0;
        op[lane + 32] = o1;
        sm0[0] += o0.x; sq0[0] += o0.x * o0.x;
        sm0[1] += o0.y; sq0[1] += o0.y * o0.y;
        sm0[2] += o0.z; sq0[2] += o0.z * o0.z;
        sm0[3] += o0.w; sq0[3] += o0.w * o0.w;
        sm1[0] += o1.x; sq1[0] += o1.x * o1.x;
        sm1[1] += o1.y; sq1[1] += o1.y * o1.y;
        sm1[2] += o1.z; sq1[2] += o1.z * o1.z;
        sm1[3] += o1.w; sq1[3] += o1.w * o1.w;
    }
    #pragma unroll
    for (int q = 0; q < 4; q++) {
        atomicAdd(&s_st[lane * 4 + q], sm0[q]);
        atomicAdd(&s_st[256 + lane * 4 + q], sq0[q]);
        atomicAdd(&s_st[128 + lane * 4 + q], sm1[q]);
        atomicAdd(&s_st[256 + 128 + lane * 4 + q], sq1[q]);
    }
    __syncthreads();
    for (int i = tid; i < 512; i += 256)
        atomicAdd(&stats[i], s_st[i]);
}

// ---- fused edge kernel, F=128 (dh=32): er + 1-pass softmax-agg ----
__global__ void k_edge128f(const int* __restrict__ rp, const int* __restrict__ srcs,
                           const float4* __restrict__ el4, const float4* __restrict__ V4,
                           const float* __restrict__ cdst, const float* __restrict__ hs,
                           float* __restrict__ out, int ndst, int fin) {
    int w = (blockIdx.x * blockDim.x + threadIdx.x) >> 5;
    int lane = threadIdx.x & 31;
    if (w >= ndst) return;
    const float* c = cdst + (size_t)w * fin;
    float a0 = 0.f, a1 = 0.f, a2 = 0.f, a3 = 0.f;
    for (int k = lane; k < fin; k += 32) {
        float xv = c[k];
        float4 v = V4[k];
        a0 += xv * v.x; a1 += xv * v.y; a2 += xv * v.z; a3 += xv * v.w;
    }
    #pragma unroll
    for (int o = 16; o; o >>= 1) {
        a0 += __shfl_xor_sync(0xffffffffu, a0, o);
        a1 += __shfl_xor_sync(0xffffffffu, a1, o);
        a2 += __shfl_xor_sync(0xffffffffu, a2, o);
        a3 += __shfl_xor_sync(0xffffffffu, a3, o);
    }
    int hsel = lane >> 3;
    float erS = (hsel == 0) ? a0 : (hsel == 1) ? a1 : (hsel == 2) ? a2 : a3;

    int s0 = rp[w], s1 = rp[w + 1];
    float4* o = (float4*)(out + (size_t)w * 128);
    if (s0 == s1) {
        o[lane] = make_float4(0.f, 0.f, 0.f, 0.f);
        return;
    }
    float4 acc = make_float4(0.f, 0.f, 0.f, 0.f);
    float z = 0.f;
    for (int j = s0; j < s1; j++) {
        int s = srcs[j];
        float4 e = el4[s];
        float eS = (hsel == 0) ? e.x : (hsel == 1) ? e.y : (hsel == 2) ? e.z : e.w;
        float a = __expf(lrelu(eS + erS, 0.2f));
        const float4* row = (const float4*)(hs + (size_t)s * 128);
        float4 v = row[lane];
        acc.x += a * v.x; acc.y += a * v.y; acc.z += a * v.z; acc.w += a * v.w;
        z += a;
    }
    float iz = 1.f / z;
    o[lane] = make_float4(acc.x * iz, acc.y * iz, acc.z * iz, acc.w * iz);
}

// ------- BN apply (+act +bf16 split), 2 columns/thread, packed stores -------
__global__ void k_bnapply(const float* __restrict__ x, float* __restrict__ y,
                          uint32_t* __restrict__ yh, uint32_t* __restrict__ yl,
                          const float* __restrict__ bn, const float* __restrict__ stats,
                          int L, int n, int use_tanh) {
    int tid = threadIdx.x;
    int cp = (tid & 127) * 2;        // column pair
    int rh = tid >> 7;               // row phase 0/1
    float inv_n = 1.f / (float)n;
    float mu0 = stats[cp] * inv_n;
    float mu1 = stats[cp + 1] * inv_n;
    float var0 = stats[256 + cp] * inv_n - mu0 * mu0;
    float var1 = stats[256 + cp + 1] * inv_n - mu1 * mu1;
    float g0 = bn[(L * 2 + 0) * 256 + cp], g1 = bn[(L * 2 + 0) * 256 + cp + 1];
    float b0 = bn[(L * 2 + 1) * 256 + cp], b1 = bn[(L * 2 + 1) * 256 + cp + 1];
    float sc0 = g0 * rsqrtf(var0 + 1e-5f), sc1 = g1 * rsqrtf(var1 + 1e-5f);
    float sh0 = b0 - mu0 * sc0, sh1 = b1 - mu1 * sc1;
    for (int r = blockIdx.x * 2 + rh; r < n; r += gridDim.x * 2) {
        size_t idx = (size_t)r * 256 + cp;
        float2 v = *(const float2*)(x + idx);
        float v0 = sc0 * v.x + sh0;
        float v1 = sc1 * v.y + sh1;
        if (use_tanh) { v0 = fast_tanh(v0); v1 = fast_tanh(v1); }
        else {
            v0 = v0 > 0.f ? v0 : 0.01f * v0;
            v1 = v1 > 0.f ? v1 : 0.01f * v1;
        }
        *(float2*)(y + idx) = make_float2(v0, v1);
        float h0 = __bfloat162float(__float2bfloat16_rn(v0));
        float h1 = __bfloat162float(__float2bfloat16_rn(v1));
        yh[idx >> 1] = pack_bf16x2(v0, v1);
        yl[idx >> 1] = pack_bf16x2(v0 - h0, v1 - h1);
    }
}

// ---------------- static stream/event setup (pre-checkpoint) ----------------
namespace {
struct StreamInit {
    cudaStream_t s2 = 0;
    cudaEvent_t ev[32];
    bool ok = false;
    StreamInit() {
        if (cudaStreamCreateWithFlags(&s2, cudaStreamNonBlocking) != cudaSuccess) return;
        for (int i = 0; i < 32; i++)
            if (cudaEventCreateWithFlags(&ev[i], cudaEventDisableTiming) != cudaSuccess)
                return;
        k_noop<<<1, 32>>>();
        k_noop<<<1, 32, 0, s2>>>();
        for (int i = 0; i < 32; i++) cudaEventRecord(ev[i], (i & 1) ? s2 : 0);
        if (cudaDeviceSynchronize() != cudaSuccess) return;
        if (cudaGetLastError() != cudaSuccess) return;
        ok = true;
    }
};
StreamInit g_si;
}

// ---------------- host orchestration ----------------
static inline int wgrid(int nwarp) { return (nwarp * 32 + 255) / 256; }

struct Ptrs {
    float *hu, *hi, *hsu, *hsi, *nu, *ni;
    float *el_u, *el_i, *Vui, *Viu, *stats_i, *stats_u;
    __nv_bfloat16 *WHu, *WLu, *WHi, *WLi, *Auh, *Aul, *Aih, *Ail;
    int *rp_i, *rp_u, *srcs_i, *srcs_u, *cur_i, *cur_u, *part;
};

static void get_ptrs(Ptrs& p) {
    cudaGetSymbolAddress((void**)&p.hu, g_hu);
    cudaGetSymbolAddress((void**)&p.hi, g_hi);
    cudaGetSymbolAddress((void**)&p.hsu, g_hsu);
    cudaGetSymbolAddress((void**)&p.hsi, g_hsi);
    cudaGetSymbolAddress((void**)&p.nu, g_nu);
    cudaGetSymbolAddress((void**)&p.ni, g_ni);
    cudaGetSymbolAddress((void**)&p.el_u, g_el_u);
    cudaGetSymbolAddress((void**)&p.el_i, g_el_i);
    cudaGetSymbolAddress((void**)&p.Vui, g_Vui);
    cudaGetSymbolAddress((void**)&p.Viu, g_Viu);
    cudaGetSymbolAddress((void**)&p.stats_i, g_stats_i);
    cudaGetSymbolAddress((void**)&p.stats_u, g_stats_u);
    cudaGetSymbolAddress((void**)&p.WHu, g_WHu);
    cudaGetSymbolAddress((void**)&p.WLu, g_WLu);
    cudaGetSymbolAddress((void**)&p.WHi, g_WHi);
    cudaGetSymbolAddress((void**)&p.WLi, g_WLi);
    cudaGetSymbolAddress((void**)&p.Auh, g_Auh);
    cudaGetSymbolAddress((void**)&p.Aul, g_Aul);
    cudaGetSymbolAddress((void**)&p.Aih, g_Aih);
    cudaGetSymbolAddress((void**)&p.Ail, g_Ail);
    cudaGetSymbolAddress((void**)&p.rp_i, g_rp_i);
    cudaGetSymbolAddress((void**)&p.rp_u, g_rp_u);
    cudaGetSymbolAddress((void**)&p.srcs_i, g_srcs_i);
    cudaGetSymbolAddress((void**)&p.srcs_u, g_srcs_u);
    cudaGetSymbolAddress((void**)&p.cur_i, g_cur_i);
    cudaGetSymbolAddress((void**)&p.cur_u, g_cur_u);
    cudaGetSymbolAddress((void**)&p.part, g_part);
}

#define SMEM256 (2 * (2 * 128 * 80 + 2 * 32 * (256 * 2 + 16)))
#define SMEM128 (2 * (2 * 128 * 80 + 2 * 32 * (128 * 2 + 16)))
#define EDGE_BLOCKS 592

static const int WOFF[4] = {0, 32768, 98304, 163840};
static const int WSZ[4]  = {32768, 65536, 65536, 32768};
#define VOFF(L) ((L) * FHID * NHEAD)

static void scan(const int* cnt, int n, int* rp, int* part, cudaStream_t st) {
    int nb = (n + 1023) / 1024;
    k_scan_blk<<<nb, 1024, 0, st>>>(cnt, n, rp, part);
    k_scan_part<<<1, 64, 0, st>>>(part, nb);
    k_scan_add<<<nb, 1024, 0, st>>>(rp, part, n);
}

static void split4(const float* X, __nv_bfloat16* xh, __nv_bfloat16* xl, int total,
                   cudaStream_t st) {
    int t4 = total >> 2;
    k_split4<<<(t4 + 255) / 256, 256, 0, st>>>((const float4*)X, (uint2*)xh,
                                               (uint2*)xl, t4);
}

extern "C" void kernel_launch(void* const* d_in, const int* in_sizes, int n_in,
                              void* d_out, int out_size) {
    Ptrs p;
    get_ptrs(p);
    cudaFuncSetAttribute(k_mma_gemm<256, 64>,
                         cudaFuncAttributeMaxDynamicSharedMemorySize, SMEM256);
    cudaFuncSetAttribute(k_mma_gemm<128, 32>,
                         cudaFuncAttributeMaxDynamicSharedMemorySize, SMEM128);

    const float* x_user = (const float*)d_in[0];
    const float* x_item = (const float*)d_in[1];
    const int*   eu     = (const int*)d_in[2];
    const int*   ei     = (const int*)d_in[3];

    bool dictOrder = (in_sizes[5] < 10000);
    const float *Wui[4], *Aui[4], *Wiu[4], *Aiu[4];
    for (int L = 0; L < 4; L++) {
        if (dictOrder) {
            Wui[L] = (const float*)d_in[4 + L * 4 + 0];
            Aui[L] = (const float*)d_in[4 + L * 4 + 1];
            Wiu[L] = (const float*)d_in[4 + L * 4 + 2];
            Aiu[L] = (const float*)d_in[4 + L * 4 + 3];
        } else {
            Wui[L] = (const float*)d_in[4 + L * 4 + 0];
            Wiu[L] = (const float*)d_in[4 + L * 4 + 1];
            Aui[L] = (const float*)d_in[4 + L * 4 + 2];
            Aiu[L] = (const float*)d_in[4 + L * 4 + 3];
        }
    }
    const float* bn_u = (const float*)d_in[20];
    const float* bn_i = (const float*)d_in[21];
    float* out = (float*)d_out;

    cudaStream_t SA = 0;
    cudaStream_t SB = g_si.ok ? g_si.s2 : (cudaStream_t)0;
    bool fork = g_si.ok;
    int ec = 0;
    auto REC = [&](cudaStream_t st) -> int {
        if (!fork) return -1;
        int i = ec++;
        cudaEventRecord(g_si.ev[i], st);
        return i;
    };
    auto WAITE = [&](cudaStream_t st, int i) {
        if (fork && i >= 0) cudaStreamWaitEvent(st, g_si.ev[i], 0);
    };

    // ---- capture-legal fork ----
    int evFork = REC(SA);
    WAITE(SB, evFork);

    // ---- SA prologue ----
    k_zerof<<<6, 256, 0, SA>>>(p.stats_i, 3 * 512);
    split4(x_user, p.Auh, p.Aul, NUSR * FIN0, SA);
    split4(Wui[0], p.WHu + WOFF[0], p.WLu + WOFF[0], WSZ[0], SA);

    // ---- SB prologue ----
    split4(x_item, p.Aih, p.Ail, NITM * FIN0, SB);
    k_zeroi<<<(NUSR + 255) / 256, 256, 0, SB>>>(p.cur_u, NUSR);
    k_zeroi<<<(NITM + 255) / 256, 256, 0, SB>>>(p.cur_i, NITM);
    k_count<<<(NEDG + 255) / 256, 256, 0, SB>>>(eu, ei, p.cur_u, p.cur_i);
    scan(p.cur_i, NITM, p.rp_i, p.part, SB);
    scan(p.cur_u, NUSR, p.rp_u, p.part, SB);
    k_copyi<<<(NITM + 255) / 256, 256, 0, SB>>>(p.rp_i, p.cur_i, NITM);
    k_copyi<<<(NUSR + 255) / 256, 256, 0, SB>>>(p.rp_u, p.cur_u, NUSR);
    k_scatter<<<(NEDG + 255) / 256, 256, 0, SB>>>(eu, ei, p.cur_u, p.cur_i,
                                                  p.srcs_u, p.srcs_i);
    {
        CVArgs cva;
        for (int L = 0; L < 4; L++) {
            cva.W[L] = Wui[L];  cva.A[L] = Aui[L];
            cva.W[4 + L] = Wiu[L];  cva.A[4 + L] = Aiu[L];
        }
        k_collapseAll<<<28, 256, 0, SB>>>(cva, p.Vui, p.Viu);
    }
    int evPre = REC(SB);
    k_zerof<<<6, 256, 0, SB>>>(p.stats_u, 3 * 512);
    split4(Wiu[0], p.WHi + WOFF[0], p.WLi + WOFF[0], WSZ[0], SB);

    const float* cu = x_user;
    const float* ci = x_item;
    int fin = FIN0;
    for (int L = 0; L < 4; L++) {
        int F = (L == 3) ? 128 : 256;
        float* outi = (L == 3) ? (out + (size_t)NUSR * 128) : p.ni;
        float* outu = (L == 3) ? out : p.nu;
        int gbU = (NUSR + 127) / 128, gbI = (NITM + 127) / 128;

        // ---- SA: user GEMM (+el_u) ----
        if (F == 256)
            k_mma_gemm<256, 64><<<gbU, 512, SMEM256, SA>>>(p.Auh, p.Aul,
                p.WHu + WOFF[L], p.WLu + WOFF[L], Aui[L], p.hsu, p.el_u, NUSR, fin);
        else
            k_mma_gemm<128, 32><<<gbU, 256, SMEM128, SA>>>(p.Auh, p.Aul,
                p.WHu + WOFF[L], p.WLu + WOFF[L], Aui[L], p.hsu, p.el_u, NUSR, fin);
        int evAg = REC(SA);

        // ---- SB: item GEMM (+el_i) ----
        if (F == 256)
            k_mma_gemm<256, 64><<<gbI, 512, SMEM256, SB>>>(p.Aih, p.Ail,
                p.WHi + WOFF[L], p.WLi + WOFF[L], Aiu[L], p.hsi, p.el_i, NITM, fin);
        else
            k_mma_gemm<128, 32><<<gbI, 256, SMEM128, SB>>>(p.Aih, p.Ail,
                p.WHi + WOFF[L], p.WLi + WOFF[L], Aiu[L], p.hsi, p.el_i, NITM, fin);
        int evBg = REC(SB);

        // ---- deferred weight splits for L1..3 ----
        if (L == 0) {
            for (int l = 1; l < 4; l++) {
                split4(Wui[l], p.WHu + WOFF[l], p.WLu + WOFF[l], WSZ[l], SA);
                split4(Wiu[l], p.WHi + WOFF[l], p.WLi + WOFF[l], WSZ[l], SB);
            }
        }

        // ---- fused edges ----
        if (L == 0) WAITE(SA, evPre);
        if (F == 256) {
            k_edge256s<<<EDGE_BLOCKS, 256, 0, SA>>>(p.rp_i, p.srcs_i,
                (const float4*)p.el_u, (const float4*)(p.Vui + VOFF(L)), ci,
                p.hsu, outi, p.stats_i + L * 512, NITM, fin);
            k_edge256s<<<EDGE_BLOCKS, 256, 0, SB>>>(p.rp_u, p.srcs_u,
                (const float4*)p.el_i, (const float4*)(p.Viu + VOFF(L)), cu,
                p.hsi, outu, p.stats_u + L * 512, NUSR, fin);
        } else {
            k_edge128f<<<wgrid(NITM), 256, 0, SA>>>(p.rp_i, p.srcs_i,
                (const float4*)p.el_u, (const float4*)(p.Vui + VOFF(L)), ci,
                p.hsu, outi, NITM, fin);
            k_edge128f<<<wgrid(NUSR), 256, 0, SB>>>(p.rp_u, p.srcs_u,
                (const float4*)p.el_i, (const float4*)(p.Viu + VOFF(L)), cu,
                p.hsi, outu, NUSR, fin);
        }

        if (L < 3) {
            WAITE(SA, evBg);
            k_bnapply<<<256, 256, 0, SA>>>(p.ni, p.hi, (uint32_t*)p.Aih,
                                           (uint32_t*)p.Ail, bn_i,
                                           p.stats_i + L * 512, L, NITM,
                                           (L == 2) ? 1 : 0);
            WAITE(SB, evAg);
            k_bnapply<<<256, 256, 0, SB>>>(p.nu, p.hu, (uint32_t*)p.Auh,
                                           (uint32_t*)p.Aul, bn_u,
                                           p.stats_u + L * 512, L, NUSR,
                                           (L == 2) ? 1 : 0);
            int evAe = REC(SA);
            int evBe = REC(SB);
            WAITE(SA, evBe);
            WAITE(SB, evAe);
            cu = p.hu;
            ci = p.hi;
            fin = FHID;
        } else {
            int evBf = REC(SB);
            WAITE(SA, evBf);
        }
    }
    (void)n_in; (void)out_size;
}